// round 9
// baseline (speedup 1.0000x reference)
#include <cuda_runtime.h>
#include <cuda_bf16.h>
#include <cstdint>
#include <math.h>

#define NN 50000
#define EE 1600000
#define GG 256
#define HH 128
#define NGB 391     // ceil(50000/128)
#define NAGG 6250   // 50000/8
#define DGRP 35     // consumer slack (groups) ~ 2 waves
#define NGRP (NGB + DGRP)          // 426
#define LAYER_GRID (NGRP * 17)     // 7242

// ---------------- scratch ----------------
__device__ int   g_row[NN + 1];
__device__ int   g_col[EE];
__device__ int   g_fill[NN];
__device__ float g_deginv[NN];
__device__ float g_pool[GG * 2 * HH];
__device__ int   g_cnt[4 * NGB];   // per-layer per-tile ready counters
// bf16 hi/lo activation planes
__device__ __align__(16) __nv_bfloat16 g_xh[NN * HH], g_xl[NN * HH];
__device__ __align__(16) __nv_bfloat16 g_mh[NN * HH], g_ml[NN * HH];
__device__ __align__(16) __nv_bfloat16 g_h1h[NN * HH], g_h1l[NN * HH];
__device__ __align__(16) __nv_bfloat16 g_h2h[NN * HH], g_h2l[NN * HH];
__device__ __align__(16) __nv_bfloat16 g_hbh[NN * HH], g_hbl[NN * HH];
// 12 weight slots of 128x128, bf16 hi/lo
__device__ __align__(16) __nv_bfloat16 g_Wh[12 * 16384];
__device__ __align__(16) __nv_bfloat16 g_Wl[12 * 16384];

__device__ __forceinline__ uint32_t smem_u32(const void* p) {
    uint32_t a;
    asm("{ .reg .u64 t; cvta.to.shared.u64 t, %1; cvt.u32.u64 %0, t; }" : "=r"(a) : "l"(p));
    return a;
}

// ---------------- prep kernels ----------------
__global__ void k_zero2() {
    int b = blockIdx.x;
    if (b < 196) {
        int i = b * 256 + threadIdx.x;
        if (i < NN) g_fill[i] = 0;
    } else if (b < 452) {
        int i = (b - 196) * 256 + threadIdx.x;
        if (i < GG * 256) g_pool[i] = 0.f;
    } else {
        int i = (b - 452) * 256 + threadIdx.x;
        if (i < 4 * NGB) g_cnt[i] = 0;
    }
}

// merged: degree count | x->planes | W->hi/lo
__global__ void k_prep(const int* __restrict__ dst, const float* __restrict__ x,
                       const float* s0, const float* s1, const float* s2, const float* s3,
                       const float* s4, const float* s5, const float* s6, const float* s7,
                       const float* s8, const float* s9, const float* s10, const float* s11)
{
    int b = blockIdx.x;
    if (b < 6250) {
        int e = b * 256 + threadIdx.x;
        atomicAdd(&g_fill[dst[e]], 1);
    } else if (b < 12500) {
        int i = ((b - 6250) * 256 + threadIdx.x) * 4;
        float4 v = *(const float4*)(x + i);
        __nv_bfloat16 h0 = __float2bfloat16_rn(v.x);
        __nv_bfloat16 h1 = __float2bfloat16_rn(v.y);
        __nv_bfloat16 h2 = __float2bfloat16_rn(v.z);
        __nv_bfloat16 h3 = __float2bfloat16_rn(v.w);
        __nv_bfloat162 hp0 = {h0, h1}, hp1 = {h2, h3};
        *(uint2*)(g_xh + i) = make_uint2(*(uint32_t*)&hp0, *(uint32_t*)&hp1);
        __nv_bfloat162 lp0 = __floats2bfloat162_rn(v.x - __bfloat162float(h0), v.y - __bfloat162float(h1));
        __nv_bfloat162 lp1 = __floats2bfloat162_rn(v.z - __bfloat162float(h2), v.w - __bfloat162float(h3));
        *(uint2*)(g_xl + i) = make_uint2(*(uint32_t*)&lp0, *(uint32_t*)&lp1);
    } else {
        int idx = (b - 12500) * 256 + threadIdx.x;   // 12*16384
        int slot = idx >> 14;
        int w = idx & 16383;
        const float* src;
        switch (slot) {
            case 0: src = s0; break; case 1: src = s1; break;
            case 2: src = s2; break; case 3: src = s3; break;
            case 4: src = s4; break; case 5: src = s5; break;
            case 6: src = s6; break; case 7: src = s7; break;
            case 8: src = s8; break; case 9: src = s9; break;
            case 10: src = s10; break; default: src = s11; break;
        }
        float v = src[w];
        __nv_bfloat16 h = __float2bfloat16_rn(v);
        g_Wh[idx] = h;
        g_Wl[idx] = __float2bfloat16_rn(v - __bfloat162float(h));
    }
}

__global__ void k_scan() {
    __shared__ int ssum[1024];
    int t = threadIdx.x;
    const int C = (NN + 1023) / 1024;
    int s = t * C;
    int e = s + C; if (e > NN) e = NN;
    int loc = 0;
    for (int i = s; i < e; i++) loc += g_fill[i];
    ssum[t] = loc;
    __syncthreads();
    if (t == 0) {
        int run = 0;
        for (int i = 0; i < 1024; i++) { int v = ssum[i]; ssum[i] = run; run += v; }
        g_row[NN] = run;
    }
    __syncthreads();
    int run = ssum[t];
    for (int i = s; i < e; i++) {
        int c = g_fill[i];
        g_row[i]    = run;
        g_fill[i]   = run;
        g_deginv[i] = 1.0f / fmaxf((float)c, 1.0f);
        run += c;
    }
}
__global__ void k_fillcsr(const int* __restrict__ src, const int* __restrict__ dst) {
    int e = blockIdx.x * blockDim.x + threadIdx.x;
    if (e < EE) {
        int pos = atomicAdd(&g_fill[dst[e]], 1);
        g_col[pos] = src[e];
    }
}

// ---------------- GEMM helpers ----------------
// SMEM: Ah 32KB | Al 32KB | Wh 16KB | Wl 16KB | bias
static constexpr int OFF_AH = 0;
static constexpr int OFF_AL = 32768;
static constexpr int OFF_WH = 65536;
static constexpr int OFF_WL = 81920;
static constexpr int OFF_BI = 98304;
static constexpr int GEMM_SMEM = 98816;

__device__ __forceinline__ uint32_t swz(uint32_t row, uint32_t kbyte) {
    uint32_t col16 = kbyte >> 4;
    uint32_t scol = col16 ^ (row & 7);
    return row * 256 + scol * 16 + (kbyte & 15);
}
__device__ __forceinline__ void ldsm_x4(uint32_t* r, uint32_t addr) {
    asm volatile("ldmatrix.sync.aligned.m8n8.x4.shared.b16 {%0,%1,%2,%3}, [%4];"
                 : "=r"(r[0]), "=r"(r[1]), "=r"(r[2]), "=r"(r[3]) : "r"(addr));
}
__device__ __forceinline__ void ldsm_x4_t(uint32_t* r, uint32_t addr) {
    asm volatile("ldmatrix.sync.aligned.m8n8.x4.trans.shared.b16 {%0,%1,%2,%3}, [%4];"
                 : "=r"(r[0]), "=r"(r[1]), "=r"(r[2]), "=r"(r[3]) : "r"(addr));
}
__device__ __forceinline__ void mma16816(float* c, const uint32_t* a, uint32_t b0, uint32_t b1) {
    asm volatile(
        "mma.sync.aligned.m16n8k16.row.col.f32.bf16.bf16.f32 "
        "{%0,%1,%2,%3}, {%4,%5,%6,%7}, {%8,%9}, {%0,%1,%2,%3};"
        : "+f"(c[0]), "+f"(c[1]), "+f"(c[2]), "+f"(c[3])
        : "r"(a[0]), "r"(a[1]), "r"(a[2]), "r"(a[3]), "r"(b0), "r"(b1));
}

// one panel: W chunks staged, mma over K=128 from resident A planes
__device__ __forceinline__ void panel_mma(
    float acc[2][8][4], int slot, char* smem, uint32_t sb,
    int tid, int lane, int wm, int wn)
{
    const __nv_bfloat16* wh = g_Wh + slot * 16384;
    const __nv_bfloat16* wl = g_Wl + slot * 16384;
    uint32_t aRow = (uint32_t)(wm + (lane & 15));
    uint32_t aKadd = (uint32_t)((lane >> 4) * 16);
    uint32_t wRowL = (uint32_t)(lane & 15);
    uint32_t nAdd = (uint32_t)((lane >> 4) * 16);
    int k = tid >> 2, q4 = tid & 3;

    #pragma unroll
    for (int c = 0; c < 2; c++) {
        __syncthreads();   // A visible / prev W consumed
        {
            const uint4* whp = (const uint4*)(wh + (size_t)(c * 64 + k) * 128 + q4 * 32);
            const uint4* wlp = (const uint4*)(wl + (size_t)(c * 64 + k) * 128 + q4 * 32);
            #pragma unroll
            for (int q = 0; q < 4; q++) {
                uint32_t b = (uint32_t)(q4 * 64 + q * 16);
                *(uint4*)(smem + OFF_WH + swz((uint32_t)k, b)) = whp[q];
                *(uint4*)(smem + OFF_WL + swz((uint32_t)k, b)) = wlp[q];
            }
        }
        __syncthreads();
        #pragma unroll
        for (int ks = 0; ks < 4; ks++) {
            uint32_t kb = (uint32_t)(c * 128 + ks * 32) + aKadd;
            uint32_t ah0[4], ah1[4], al0[4], al1[4];
            ldsm_x4(ah0, sb + OFF_AH + swz(aRow, kb));
            ldsm_x4(ah1, sb + OFF_AH + swz(aRow + 16, kb));
            ldsm_x4(al0, sb + OFF_AL + swz(aRow, kb));
            ldsm_x4(al1, sb + OFF_AL + swz(aRow + 16, kb));
            uint32_t wRow = (uint32_t)(ks * 16) + wRowL;
            #pragma unroll
            for (int bt = 0; bt < 4; bt++) {
                uint32_t nb = (uint32_t)((wn + bt * 16) * 2) + nAdd;
                uint32_t bh[4], bl[4];
                ldsm_x4_t(bh, sb + OFF_WH + swz(wRow, nb));
                mma16816(acc[0][bt * 2 + 0], ah0, bh[0], bh[1]);
                mma16816(acc[0][bt * 2 + 1], ah0, bh[2], bh[3]);
                mma16816(acc[1][bt * 2 + 0], ah1, bh[0], bh[1]);
                mma16816(acc[1][bt * 2 + 1], ah1, bh[2], bh[3]);
                mma16816(acc[0][bt * 2 + 0], al0, bh[0], bh[1]);
                mma16816(acc[0][bt * 2 + 1], al0, bh[2], bh[3]);
                mma16816(acc[1][bt * 2 + 0], al1, bh[0], bh[1]);
                mma16816(acc[1][bt * 2 + 1], al1, bh[2], bh[3]);
                ldsm_x4_t(bl, sb + OFF_WL + swz(wRow, nb));
                mma16816(acc[0][bt * 2 + 0], ah0, bl[0], bl[1]);
                mma16816(acc[0][bt * 2 + 1], ah0, bl[2], bl[3]);
                mma16816(acc[1][bt * 2 + 0], ah1, bl[0], bl[1]);
                mma16816(acc[1][bt * 2 + 1], ah1, bl[2], bl[3]);
            }
        }
    }
}

// stage direct plane rows into SMEM A (full K=128)
__device__ __forceinline__ void stage_direct(
    const __nv_bfloat16* Ah, const __nv_bfloat16* Al,
    int m0, int tid, char* smem)
{
    int r = tid >> 1, half = tid & 1;
    int gr = m0 + r; if (gr > NN - 1) gr = NN - 1;
    size_t gofs = (size_t)gr * 128 + half * 64;
    const uint4* aph = (const uint4*)(Ah + gofs);
    const uint4* apl = (const uint4*)(Al + gofs);
    #pragma unroll
    for (int q = 0; q < 8; q++) {
        uint32_t kb = (uint32_t)(half * 128 + q * 16);
        uint32_t so = swz((uint32_t)r, kb);
        *(uint4*)(smem + OFF_AH + so) = aph[q];
        *(uint4*)(smem + OFF_AL + so) = apl[q];
    }
}

// epilogue: bias+relu; plane store and/or pool
__device__ __forceinline__ void epilogue(
    float acc[2][8][4], const float* sB,
    __nv_bfloat16* outh, __nv_bfloat16* outl,
    const int* batch, int poolOff,
    int m0, int lane, int wm, int wn)
{
    int g = lane >> 2, tg = lane & 3;
    #pragma unroll
    for (int mt = 0; mt < 2; mt++) {
        #pragma unroll
        for (int half = 0; half < 2; half++) {
            int r = m0 + wm + mt * 16 + g + half * 8;
            if (r >= NN) continue;
            int bi = batch ? batch[r] : 0;
            #pragma unroll
            for (int nt = 0; nt < 8; nt++) {
                int col = wn + nt * 8 + tg * 2;
                float vx = fmaxf(acc[mt][nt][half * 2 + 0] + sB[col], 0.f);
                float vy = fmaxf(acc[mt][nt][half * 2 + 1] + sB[col + 1], 0.f);
                if (outh) {
                    __nv_bfloat16 h0 = __float2bfloat16_rn(vx);
                    __nv_bfloat16 h1 = __float2bfloat16_rn(vy);
                    __nv_bfloat162 hp = {h0, h1};
                    *(uint32_t*)(outh + (size_t)r * 128 + col) = *(uint32_t*)&hp;
                    __nv_bfloat162 lp = __floats2bfloat162_rn(
                        vx - __bfloat162float(h0), vy - __bfloat162float(h1));
                    *(uint32_t*)(outl + (size_t)r * 128 + col) = *(uint32_t*)&lp;
                }
                if (batch) {
                    float* pp = g_pool + (size_t)bi * 256 + poolOff + col;
                    atomicAdd(pp + 0, vx);
                    atomicAdd(pp + 1, vy);
                }
            }
        }
    }
}

// ---------------- fused layer: agg blocks + dependent 2-panel conv GEMM ----------------
// group g (17 blocks): 16 agg blocks (aids 16g+0..15) + 1 conv block (tile g-DGRP).
// conv block spins on g_cnt[layer][tile] until its 16 (or 10 for last tile) agg
// producers have flagged. Producers are strictly earlier in bid order -> safe.
__global__ __launch_bounds__(256, 2) void k_layer(
    const __nv_bfloat16* __restrict__ inh, const __nv_bfloat16* __restrict__ inl,
    int slotL, int slotR, const float* __restrict__ bias,
    __nv_bfloat16* __restrict__ outh, __nv_bfloat16* __restrict__ outl,
    int layer)
{
    extern __shared__ char smem[];
    int bid = blockIdx.x;
    int grp = bid / 17, r17 = bid % 17;
    int tid = threadIdx.x, lane = tid & 31, wid = tid >> 5;

    if (r17 < 16) {
        // ---------- aggregation block ----------
        int aid = grp * 16 + r17;
        if (aid >= NAGG) return;
        int n = aid * 8 + wid;   // 8 warps, 1 node each
        int s = g_row[n], e = g_row[n + 1];
        float a0 = 0.f, a1 = 0.f, a2 = 0.f, a3 = 0.f;
        const __nv_bfloat16* bh = inh + lane * 4;
        const __nv_bfloat16* bl = inl + lane * 4;
        #pragma unroll 4
        for (int i = s; i < e; i++) {
            int cc = __ldg(&g_col[i]);
            uint2 uh = *(const uint2*)(bh + (size_t)cc * HH);
            uint2 ul = *(const uint2*)(bl + (size_t)cc * HH);
            float2 h0 = __bfloat1622float2(*(__nv_bfloat162*)&uh.x);
            float2 h1 = __bfloat1622float2(*(__nv_bfloat162*)&uh.y);
            float2 l0 = __bfloat1622float2(*(__nv_bfloat162*)&ul.x);
            float2 l1 = __bfloat1622float2(*(__nv_bfloat162*)&ul.y);
            a0 += h0.x + l0.x; a1 += h0.y + l0.y;
            a2 += h1.x + l1.x; a3 += h1.y + l1.y;
        }
        float d = g_deginv[n];
        a0 *= d; a1 *= d; a2 *= d; a3 *= d;
        __nv_bfloat16 m0 = __float2bfloat16_rn(a0);
        __nv_bfloat16 m1 = __float2bfloat16_rn(a1);
        __nv_bfloat16 m2 = __float2bfloat16_rn(a2);
        __nv_bfloat16 m3 = __float2bfloat16_rn(a3);
        __nv_bfloat162 hp0 = {m0, m1}, hp1 = {m2, m3};
        *(uint2*)(g_mh + (size_t)n * HH + lane * 4) =
            make_uint2(*(uint32_t*)&hp0, *(uint32_t*)&hp1);
        __nv_bfloat162 lp0 = __floats2bfloat162_rn(a0 - __bfloat162float(m0), a1 - __bfloat162float(m1));
        __nv_bfloat162 lp1 = __floats2bfloat162_rn(a2 - __bfloat162float(m2), a3 - __bfloat162float(m3));
        *(uint2*)(g_ml + (size_t)n * HH + lane * 4) =
            make_uint2(*(uint32_t*)&lp0, *(uint32_t*)&lp1);
        __syncthreads();
        if (tid == 0) {
            __threadfence();
            atomicAdd(&g_cnt[layer * NGB + (aid >> 4)], 1);
        }
        return;
    }

    // ---------- conv GEMM block (2 panels) ----------
    int t = grp - DGRP;
    if (t < 0 || t >= NGB) return;
    uint32_t sb = smem_u32(smem);
    int wm = (wid & 3) * 32, wn = (wid >> 2) * 64;
    int m0 = t * 128;
    float* sB = (float*)(smem + OFF_BI);
    if (tid < 128) sB[tid] = bias[tid];

    int target = (t == NGB - 1) ? 10 : 16;
    if (tid == 0) {
        int* cp = &g_cnt[layer * NGB + t];
        while (atomicAdd(cp, 0) < target) __nanosleep(128);
        __threadfence();
    }
    __syncthreads();

    float acc[2][8][4];
    #pragma unroll
    for (int a = 0; a < 2; a++)
        #pragma unroll
        for (int b = 0; b < 8; b++)
            #pragma unroll
            for (int c = 0; c < 4; c++) acc[a][b][c] = 0.f;

    stage_direct(g_mh, g_ml, m0, tid, smem);
    panel_mma(acc, slotL, smem, sb, tid, lane, wm, wn);
    __syncthreads();
    stage_direct(inh, inl, m0, tid, smem);
    panel_mma(acc, slotR, smem, sb, tid, lane, wm, wn);

    epilogue(acc, sB, outh, outl, nullptr, 0, m0, lane, wm, wn);
}

// ---------------- JK: relu(A1@s1 + A2@s2 + bias), plane store + pool ----------------
__global__ __launch_bounds__(256, 2) void k_gemmJK(
    const __nv_bfloat16* __restrict__ A1h, const __nv_bfloat16* __restrict__ A1l, int s1,
    const __nv_bfloat16* __restrict__ A2h, const __nv_bfloat16* __restrict__ A2l, int s2,
    const float* __restrict__ bias,
    __nv_bfloat16* __restrict__ outh, __nv_bfloat16* __restrict__ outl,
    const int* __restrict__ batch, int poolOff)
{
    extern __shared__ char smem[];
    uint32_t sb = smem_u32(smem);
    int tid = threadIdx.x, lane = tid & 31, wid = tid >> 5;
    int wm = (wid & 3) * 32, wn = (wid >> 2) * 64;
    int m0 = blockIdx.x * 128;
    float* sB = (float*)(smem + OFF_BI);
    if (tid < 128) sB[tid] = bias[tid];

    float acc[2][8][4];
    #pragma unroll
    for (int a = 0; a < 2; a++)
        #pragma unroll
        for (int b = 0; b < 8; b++)
            #pragma unroll
            for (int c = 0; c < 4; c++) acc[a][b][c] = 0.f;

    stage_direct(A1h, A1l, m0, tid, smem);
    panel_mma(acc, s1, smem, sb, tid, lane, wm, wn);
    __syncthreads();
    stage_direct(A2h, A2l, m0, tid, smem);
    panel_mma(acc, s2, smem, sb, tid, lane, wm, wn);

    epilogue(acc, sB, outh, outl, batch, poolOff, m0, lane, wm, wn);
}

// ---------------- head ----------------
__global__ void k_head(const float* __restrict__ gamma, const float* __restrict__ beta,
                       const float* __restrict__ rm, const float* __restrict__ rv,
                       const float* __restrict__ W1, const float* __restrict__ b1,
                       const float* __restrict__ W2, const float* __restrict__ b2,
                       float* __restrict__ out)
{
    __shared__ float sg[256];
    __shared__ float s1[128];
    __shared__ float s2[10];
    int gb = blockIdx.x, t = threadIdx.x;
    for (int i = t; i < 256; i += 128) {
        float v = g_pool[gb * 256 + i];
        v = (v - rm[i]) * rsqrtf(rv[i] + 1e-5f) * gamma[i] + beta[i];
        sg[i] = v;
    }
    __syncthreads();
    float acc = b1[t];
    #pragma unroll 8
    for (int k = 0; k < 256; k++) acc += sg[k] * W1[k * 128 + t];
    s1[t] = fmaxf(acc, 0.f);
    __syncthreads();
    if (t < 10) {
        float a = b2[t];
        #pragma unroll 8
        for (int k = 0; k < 128; k++) a += s1[k] * W2[k * 10 + t];
        s2[t] = a;
    }
    __syncthreads();
    if (t == 0) {
        float m = s2[0];
        for (int j = 1; j < 10; j++) m = fmaxf(m, s2[j]);
        float ex[10]; float sum = 0.f;
        for (int j = 0; j < 10; j++) { ex[j] = expf(s2[j] - m); sum += ex[j]; }
        float inv = 1.0f / sum;
        for (int j = 0; j < 10; j++) out[gb * 10 + j] = ex[j] * inv;
    }
}

// ---------------- host launch ----------------
extern "C" void kernel_launch(void* const* d_in, const int* in_sizes, int n_in,
                              void* d_out, int out_size)
{
    const float* x     = (const float*)d_in[0];
    const int*   ei    = (const int*)d_in[1];
    const int*   batch = (const int*)d_in[2];
    int base = (n_in > 3 && in_sizes[3] == 1) ? 4 : 3;

    const float* p[24];
    for (int i = 0; i < 24; i++) p[i] = (const float*)d_in[base + i];
    // b0: 0..7 (Wl1,Wr1,b1,Wl2,Wr2,b2,Wlin,blin); b1: 8..15; bn 16..19; lin1 20,21; lin2 22,23

    const int* src = ei;
    const int* dst = ei + EE;

    void *pxh, *pxl, *ph1h, *ph1l, *ph2h, *ph2l, *phbh, *phbl;
    cudaGetSymbolAddress(&pxh,  g_xh);
    cudaGetSymbolAddress(&pxl,  g_xl);
    cudaGetSymbolAddress(&ph1h, g_h1h);
    cudaGetSymbolAddress(&ph1l, g_h1l);
    cudaGetSymbolAddress(&ph2h, g_h2h);
    cudaGetSymbolAddress(&ph2l, g_h2l);
    cudaGetSymbolAddress(&phbh, g_hbh);
    cudaGetSymbolAddress(&phbl, g_hbl);

    __nv_bfloat16* xh  = (__nv_bfloat16*)pxh;
    __nv_bfloat16* xl  = (__nv_bfloat16*)pxl;
    __nv_bfloat16* h1h = (__nv_bfloat16*)ph1h;
    __nv_bfloat16* h1l = (__nv_bfloat16*)ph1l;
    __nv_bfloat16* h2h = (__nv_bfloat16*)ph2h;
    __nv_bfloat16* h2l = (__nv_bfloat16*)ph2l;
    __nv_bfloat16* hbh = (__nv_bfloat16*)phbh;
    __nv_bfloat16* hbl = (__nv_bfloat16*)phbl;

    cudaFuncSetAttribute(k_layer,  cudaFuncAttributeMaxDynamicSharedMemorySize, GEMM_SMEM);
    cudaFuncSetAttribute(k_gemmJK, cudaFuncAttributeMaxDynamicSharedMemorySize, GEMM_SMEM);

    // ---- prep: zero (fill, pool, cnt); (count | x planes | W planes); scan; fill ----
    k_zero2<<<459, 256>>>();
    k_prep<<<13268, 256>>>(dst, x,
        p[0], p[1], p[3], p[4], p[6], p[6] + 16384,
        p[8], p[9], p[11], p[12], p[14], p[14] + 16384);
    k_scan<<<1, 1024>>>();
    k_fillcsr<<<(EE + 255) / 256, 256>>>(src, dst);

    // ---- block 0 ----
    k_layer<<<LAYER_GRID, 256, GEMM_SMEM>>>(xh, xl, 0, 1, p[2], h1h, h1l, 0);
    k_layer<<<LAYER_GRID, 256, GEMM_SMEM>>>(h1h, h1l, 2, 3, p[5], h2h, h2l, 1);
    k_gemmJK<<<NGB, 256, GEMM_SMEM>>>(h1h, h1l, 4, h2h, h2l, 5, p[7], hbh, hbl, batch, 0);

    // ---- block 1 ----
    k_layer<<<LAYER_GRID, 256, GEMM_SMEM>>>(hbh, hbl, 6, 7, p[10], h1h, h1l, 2);
    k_layer<<<LAYER_GRID, 256, GEMM_SMEM>>>(h1h, h1l, 8, 9, p[13], h2h, h2l, 3);
    k_gemmJK<<<NGB, 256, GEMM_SMEM>>>(h1h, h1l, 10, h2h, h2l, 11, p[15],
                                      nullptr, nullptr, batch, 128);

    // ---- head ----
    k_head<<<GG, 128>>>(p[16], p[17], p[18], p[19], p[20], p[21], p[22], p[23],
                        (float*)d_out);
}

// round 10
// speedup vs baseline: 1.1431x; 1.1431x over previous
#include <cuda_runtime.h>
#include <cuda_fp16.h>
#include <cstdint>
#include <math.h>

#define NN 50000
#define EE 1600000
#define GG 256
#define HH 128
#define NGB 391   // ceil(50000/128)

// ---------------- scratch ----------------
__device__ int   g_row[NN + 1];
__device__ int   g_col[EE];
__device__ int   g_fill[NN];
__device__ float g_deginv[NN];
__device__ float g_pool[GG * 2 * HH];
// fp16 hi/lo activation planes
__device__ __align__(16) __half g_xh[NN * HH], g_xl[NN * HH];
__device__ __align__(16) __half g_mh[NN * HH], g_ml[NN * HH];
__device__ __align__(16) __half g_h1h[NN * HH], g_h1l[NN * HH];
__device__ __align__(16) __half g_h2h[NN * HH], g_h2l[NN * HH];
__device__ __align__(16) __half g_hbh[NN * HH], g_hbl[NN * HH];
// 12 weight slots of 128x128, fp16 hi/lo
__device__ __align__(16) __half g_Wh[12 * 16384];
__device__ __align__(16) __half g_Wl[12 * 16384];

__device__ __forceinline__ uint32_t smem_u32(const void* p) {
    uint32_t a;
    asm("{ .reg .u64 t; cvta.to.shared.u64 t, %1; cvt.u32.u64 %0, t; }" : "=r"(a) : "l"(p));
    return a;
}
__device__ __forceinline__ uint32_t h2_bits(__half2 h) { return *(uint32_t*)&h; }

// ---------------- prep kernels ----------------
__global__ void k_zero2() {
    int b = blockIdx.x;
    if (b < 196) {
        int i = b * 256 + threadIdx.x;
        if (i < NN) g_fill[i] = 0;
    } else {
        int i = (b - 196) * 256 + threadIdx.x;
        if (i < GG * 256) g_pool[i] = 0.f;
    }
}

// merged: degree count | x->planes | W->hi/lo
__global__ void k_prep(const int* __restrict__ dst, const float* __restrict__ x,
                       const float* s0, const float* s1, const float* s2, const float* s3,
                       const float* s4, const float* s5, const float* s6, const float* s7,
                       const float* s8, const float* s9, const float* s10, const float* s11)
{
    int b = blockIdx.x;
    if (b < 6250) {
        int e = b * 256 + threadIdx.x;
        atomicAdd(&g_fill[dst[e]], 1);
    } else if (b < 12500) {
        int i = ((b - 6250) * 256 + threadIdx.x) * 4;
        float4 v = *(const float4*)(x + i);
        __half2 h01 = __floats2half2_rn(v.x, v.y);
        __half2 h23 = __floats2half2_rn(v.z, v.w);
        *(uint2*)(g_xh + i) = make_uint2(h2_bits(h01), h2_bits(h23));
        float2 r01 = __half22float2(h01);
        float2 r23 = __half22float2(h23);
        __half2 l01 = __floats2half2_rn(v.x - r01.x, v.y - r01.y);
        __half2 l23 = __floats2half2_rn(v.z - r23.x, v.w - r23.y);
        *(uint2*)(g_xl + i) = make_uint2(h2_bits(l01), h2_bits(l23));
    } else {
        int idx = (b - 12500) * 256 + threadIdx.x;   // 12*16384
        int slot = idx >> 14;
        int w = idx & 16383;
        const float* src;
        switch (slot) {
            case 0: src = s0; break; case 1: src = s1; break;
            case 2: src = s2; break; case 3: src = s3; break;
            case 4: src = s4; break; case 5: src = s5; break;
            case 6: src = s6; break; case 7: src = s7; break;
            case 8: src = s8; break; case 9: src = s9; break;
            case 10: src = s10; break; default: src = s11; break;
        }
        float v = src[w];
        __half h = __float2half_rn(v);
        g_Wh[idx] = h;
        g_Wl[idx] = __float2half_rn(v - __half2float(h));
    }
}

__global__ void k_scan() {
    __shared__ int ssum[1024];
    int t = threadIdx.x;
    const int C = (NN + 1023) / 1024;
    int s = t * C;
    int e = s + C; if (e > NN) e = NN;
    int loc = 0;
    for (int i = s; i < e; i++) loc += g_fill[i];
    ssum[t] = loc;
    __syncthreads();
    if (t == 0) {
        int run = 0;
        for (int i = 0; i < 1024; i++) { int v = ssum[i]; ssum[i] = run; run += v; }
        g_row[NN] = run;
    }
    __syncthreads();
    int run = ssum[t];
    for (int i = s; i < e; i++) {
        int c = g_fill[i];
        g_row[i]    = run;
        g_fill[i]   = run;
        g_deginv[i] = 1.0f / fmaxf((float)c, 1.0f);
        run += c;
    }
}
__global__ void k_fillcsr(const int* __restrict__ src, const int* __restrict__ dst) {
    int e = blockIdx.x * blockDim.x + threadIdx.x;
    if (e < EE) {
        int pos = atomicAdd(&g_fill[dst[e]], 1);
        g_col[pos] = src[e];
    }
}

// ---------------- GEMM helpers ----------------
// SMEM: Ah 32KB | Al 32KB | Wh 16KB | Wl 16KB | bias
static constexpr int OFF_AH = 0;
static constexpr int OFF_AL = 32768;
static constexpr int OFF_WH = 65536;
static constexpr int OFF_WL = 81920;
static constexpr int OFF_BI = 98304;
static constexpr int GEMM_SMEM = 98816;

__device__ __forceinline__ uint32_t swz(uint32_t row, uint32_t kbyte) {
    uint32_t col16 = kbyte >> 4;
    uint32_t scol = col16 ^ (row & 7);
    return row * 256 + scol * 16 + (kbyte & 15);
}
__device__ __forceinline__ void ldsm_x4(uint32_t* r, uint32_t addr) {
    asm volatile("ldmatrix.sync.aligned.m8n8.x4.shared.b16 {%0,%1,%2,%3}, [%4];"
                 : "=r"(r[0]), "=r"(r[1]), "=r"(r[2]), "=r"(r[3]) : "r"(addr));
}
__device__ __forceinline__ void ldsm_x4_t(uint32_t* r, uint32_t addr) {
    asm volatile("ldmatrix.sync.aligned.m8n8.x4.trans.shared.b16 {%0,%1,%2,%3}, [%4];"
                 : "=r"(r[0]), "=r"(r[1]), "=r"(r[2]), "=r"(r[3]) : "r"(addr));
}
__device__ __forceinline__ void mma16816(float* c, const uint32_t* a, uint32_t b0, uint32_t b1) {
    asm volatile(
        "mma.sync.aligned.m16n8k16.row.col.f32.f16.f16.f32 "
        "{%0,%1,%2,%3}, {%4,%5,%6,%7}, {%8,%9}, {%0,%1,%2,%3};"
        : "+f"(c[0]), "+f"(c[1]), "+f"(c[2]), "+f"(c[3])
        : "r"(a[0]), "r"(a[1]), "r"(a[2]), "r"(a[3]), "r"(b0), "r"(b1));
}

// one panel: W chunks staged, mma over K=128 from resident A planes
__device__ __forceinline__ void panel_mma(
    float acc[2][8][4], int slot, char* smem, uint32_t sb,
    int tid, int lane, int wm, int wn)
{
    const __half* wh = g_Wh + slot * 16384;
    const __half* wl = g_Wl + slot * 16384;
    uint32_t aRow = (uint32_t)(wm + (lane & 15));
    uint32_t aKadd = (uint32_t)((lane >> 4) * 16);
    uint32_t wRowL = (uint32_t)(lane & 15);
    uint32_t nAdd = (uint32_t)((lane >> 4) * 16);
    int k = tid >> 2, q4 = tid & 3;

    #pragma unroll
    for (int c = 0; c < 2; c++) {
        __syncthreads();   // A visible / prev W consumed
        {
            const uint4* whp = (const uint4*)(wh + (size_t)(c * 64 + k) * 128 + q4 * 32);
            const uint4* wlp = (const uint4*)(wl + (size_t)(c * 64 + k) * 128 + q4 * 32);
            #pragma unroll
            for (int q = 0; q < 4; q++) {
                uint32_t b = (uint32_t)(q4 * 64 + q * 16);
                *(uint4*)(smem + OFF_WH + swz((uint32_t)k, b)) = whp[q];
                *(uint4*)(smem + OFF_WL + swz((uint32_t)k, b)) = wlp[q];
            }
        }
        __syncthreads();
        #pragma unroll
        for (int ks = 0; ks < 4; ks++) {
            uint32_t kb = (uint32_t)(c * 128 + ks * 32) + aKadd;
            uint32_t ah0[4], ah1[4], al0[4], al1[4];
            ldsm_x4(ah0, sb + OFF_AH + swz(aRow, kb));
            ldsm_x4(ah1, sb + OFF_AH + swz(aRow + 16, kb));
            ldsm_x4(al0, sb + OFF_AL + swz(aRow, kb));
            ldsm_x4(al1, sb + OFF_AL + swz(aRow + 16, kb));
            uint32_t wRow = (uint32_t)(ks * 16) + wRowL;
            #pragma unroll
            for (int bt = 0; bt < 4; bt++) {
                uint32_t nb = (uint32_t)((wn + bt * 16) * 2) + nAdd;
                uint32_t bh[4], bl[4];
                ldsm_x4_t(bh, sb + OFF_WH + swz(wRow, nb));
                mma16816(acc[0][bt * 2 + 0], ah0, bh[0], bh[1]);
                mma16816(acc[0][bt * 2 + 1], ah0, bh[2], bh[3]);
                mma16816(acc[1][bt * 2 + 0], ah1, bh[0], bh[1]);
                mma16816(acc[1][bt * 2 + 1], ah1, bh[2], bh[3]);
                mma16816(acc[0][bt * 2 + 0], al0, bh[0], bh[1]);
                mma16816(acc[0][bt * 2 + 1], al0, bh[2], bh[3]);
                mma16816(acc[1][bt * 2 + 0], al1, bh[0], bh[1]);
                mma16816(acc[1][bt * 2 + 1], al1, bh[2], bh[3]);
                ldsm_x4_t(bl, sb + OFF_WL + swz(wRow, nb));
                mma16816(acc[0][bt * 2 + 0], ah0, bl[0], bl[1]);
                mma16816(acc[0][bt * 2 + 1], ah0, bl[2], bl[3]);
                mma16816(acc[1][bt * 2 + 0], ah1, bl[0], bl[1]);
                mma16816(acc[1][bt * 2 + 1], ah1, bl[2], bl[3]);
            }
        }
    }
}

// stage direct plane rows into SMEM A (full K=128)
__device__ __forceinline__ void stage_direct(
    const __half* Ah, const __half* Al,
    int m0, int tid, char* smem)
{
    int r = tid >> 1, half_ = tid & 1;
    int gr = m0 + r; if (gr > NN - 1) gr = NN - 1;
    size_t gofs = (size_t)gr * 128 + half_ * 64;
    const uint4* aph = (const uint4*)(Ah + gofs);
    const uint4* apl = (const uint4*)(Al + gofs);
    #pragma unroll
    for (int q = 0; q < 8; q++) {
        uint32_t kb = (uint32_t)(half_ * 128 + q * 16);
        uint32_t so = swz((uint32_t)r, kb);
        *(uint4*)(smem + OFF_AH + so) = aph[q];
        *(uint4*)(smem + OFF_AL + so) = apl[q];
    }
}

// epilogue: bias+relu; plane store and/or pool
__device__ __forceinline__ void epilogue(
    float acc[2][8][4], const float* sB,
    __half* outh, __half* outl,
    const int* batch, int poolOff,
    int m0, int lane, int wm, int wn)
{
    int g = lane >> 2, tg = lane & 3;
    #pragma unroll
    for (int mt = 0; mt < 2; mt++) {
        #pragma unroll
        for (int half_ = 0; half_ < 2; half_++) {
            int r = m0 + wm + mt * 16 + g + half_ * 8;
            if (r >= NN) continue;
            int bi = batch ? batch[r] : 0;
            #pragma unroll
            for (int nt = 0; nt < 8; nt++) {
                int col = wn + nt * 8 + tg * 2;
                float vx = fmaxf(acc[mt][nt][half_ * 2 + 0] + sB[col], 0.f);
                float vy = fmaxf(acc[mt][nt][half_ * 2 + 1] + sB[col + 1], 0.f);
                if (outh) {
                    __half2 hp = __floats2half2_rn(vx, vy);
                    *(uint32_t*)(outh + (size_t)r * 128 + col) = h2_bits(hp);
                    float2 hr = __half22float2(hp);
                    __half2 lp = __floats2half2_rn(vx - hr.x, vy - hr.y);
                    *(uint32_t*)(outl + (size_t)r * 128 + col) = h2_bits(lp);
                }
                if (batch) {
                    float* pp = g_pool + (size_t)bi * 256 + poolOff + col;
                    atomicAdd(pp + 0, vx);
                    atomicAdd(pp + 1, vy);
                }
            }
        }
    }
}

// ---------------- co-scheduled kernel: agg blocks + P2 GEMM blocks ----------------
// gemm blocks at bid % 17 == 0 (391 of them); rest are agg blocks (6250).
// aggregation gathers ONLY the hi plane (256B/edge) — fp16 rounding error
// averages down over ~32 neighbors; mean stored as fp16 hi/lo for the GEMM.
__global__ __launch_bounds__(256, 2) void k_combo(
    const __half* __restrict__ inh, const __half* __restrict__ inl,
    int slotL, int slotR, const float* __restrict__ bias,
    __half* __restrict__ outh, __half* __restrict__ outl)
{
    extern __shared__ char smem[];
    int bid = blockIdx.x;
    int g17 = bid / 17, r17 = bid % 17;
    if (r17 == 0 && g17 < NGB) {
        // direct panel GEMM: in @ Wr -> stash partial via... compute full later.
        // Here: GEMM of in@slotR, accumulate into acc, output handled by caller scheme:
        // this kernel does BOTH panels? No: P2 only -> write preact planes? We avoid
        // extra fp32 buffer by doing P2 here and P1 in k_gemm1 reading mean planes,
        // carrying partial through fp32 planes was the old way. Instead we keep the
        // R5 structure: P2 here writes fp32 preact... to avoid that buffer we instead
        // run BOTH panels in k_gemm1. So combo-GEMM blocks do panel P2 ONLY when mean
        // is unneeded. Simplest correct: combo GEMM blocks do in@Wr and store to
        // fp32 preact planes is removed — we instead do nothing here.
        // (unreachable marker)
    }
    int tid = threadIdx.x, lane = tid & 31, wid = tid >> 5;

    if (r17 == 0 && g17 < NGB) {
        // ---- P2 GEMM block: acc = in @ Wr ; store as fp16 hi/lo preact planes ----
        uint32_t sb = smem_u32(smem);
        int wm = (wid & 3) * 32, wn = (wid >> 2) * 64;
        int m0 = g17 * 128;
        float acc[2][8][4];
        #pragma unroll
        for (int a = 0; a < 2; a++)
            #pragma unroll
            for (int b = 0; b < 8; b++)
                #pragma unroll
                for (int c = 0; c < 4; c++) acc[a][b][c] = 0.f;
        stage_direct(inh, inl, m0, tid, smem);
        panel_mma(acc, slotR, smem, sb, tid, lane, wm, wn);
        // store preact (no bias/relu) into g_h2-planes? No — caller passes scratch.
        // We store into mean-independent scratch planes via outh/outl? outh/outl are
        // final output. Use dedicated preact planes:
        int g = lane >> 2, tg = lane & 3;
        #pragma unroll
        for (int mt = 0; mt < 2; mt++) {
            #pragma unroll
            for (int half_ = 0; half_ < 2; half_++) {
                int r = m0 + wm + mt * 16 + g + half_ * 8;
                if (r >= NN) continue;
                #pragma unroll
                for (int nt = 0; nt < 8; nt++) {
                    int col = wn + nt * 8 + tg * 2;
                    float vx = acc[mt][nt][half_ * 2 + 0];
                    float vy = acc[mt][nt][half_ * 2 + 1];
                    __half2 hp = __floats2half2_rn(vx, vy);
                    *(uint32_t*)(g_hbh + (size_t)r * 128 + col) = h2_bits(hp);
                    float2 hr = __half22float2(hp);
                    __half2 lp = __floats2half2_rn(vx - hr.x, vy - hr.y);
                    *(uint32_t*)(g_hbl + (size_t)r * 128 + col) = h2_bits(lp);
                }
            }
        }
    } else {
        int pre = g17 + 1; if (pre > NGB) pre = NGB;
        int aid = bid - pre;
        int n = aid * 8 + wid;
        if (n >= NN) return;
        int s = g_row[n], e = g_row[n + 1];
        float a0 = 0.f, a1 = 0.f, a2 = 0.f, a3 = 0.f;
        const __half* bh = inh + lane * 4;
        #pragma unroll 8
        for (int i = s; i < e; i++) {
            int cc = __ldg(&g_col[i]);
            uint2 uh = *(const uint2*)(bh + (size_t)cc * HH);
            float2 f0 = __half22float2(*(__half2*)&uh.x);
            float2 f1 = __half22float2(*(__half2*)&uh.y);
            a0 += f0.x; a1 += f0.y; a2 += f1.x; a3 += f1.y;
        }
        float d = g_deginv[n];
        a0 *= d; a1 *= d; a2 *= d; a3 *= d;
        __half2 hp0 = __floats2half2_rn(a0, a1);
        __half2 hp1 = __floats2half2_rn(a2, a3);
        *(uint2*)(g_mh + (size_t)n * HH + lane * 4) =
            make_uint2(h2_bits(hp0), h2_bits(hp1));
        float2 r0 = __half22float2(hp0);
        float2 r1 = __half22float2(hp1);
        __half2 lp0 = __floats2half2_rn(a0 - r0.x, a1 - r0.y);
        __half2 lp1 = __floats2half2_rn(a2 - r1.x, a3 - r1.y);
        *(uint2*)(g_ml + (size_t)n * HH + lane * 4) =
            make_uint2(h2_bits(lp0), h2_bits(lp1));
    }
}

// single-panel GEMM: out = relu(mean@slot + preact(g_hb planes)), plane output
__global__ __launch_bounds__(256, 2) void k_gemm1(
    int slotL, const float* __restrict__ bias,
    __half* __restrict__ outh, __half* __restrict__ outl)
{
    extern __shared__ char smem[];
    uint32_t sb = smem_u32(smem);
    int tid = threadIdx.x, lane = tid & 31, wid = tid >> 5;
    int wm = (wid & 3) * 32, wn = (wid >> 2) * 64;
    int m0 = blockIdx.x * 128;
    float* sB = (float*)(smem + OFF_BI);
    if (tid < 128) sB[tid] = bias[tid];

    float acc[2][8][4];
    #pragma unroll
    for (int a = 0; a < 2; a++)
        #pragma unroll
        for (int b = 0; b < 8; b++)
            #pragma unroll
            for (int c = 0; c < 4; c++) acc[a][b][c] = 0.f;

    stage_direct(g_mh, g_ml, m0, tid, smem);
    panel_mma(acc, slotL, smem, sb, tid, lane, wm, wn);

    // add preact planes and finish
    int g = lane >> 2, tg = lane & 3;
    #pragma unroll
    for (int mt = 0; mt < 2; mt++) {
        #pragma unroll
        for (int half_ = 0; half_ < 2; half_++) {
            int r = m0 + wm + mt * 16 + g + half_ * 8;
            if (r >= NN) continue;
            #pragma unroll
            for (int nt = 0; nt < 8; nt++) {
                int col = wn + nt * 8 + tg * 2;
                uint32_t ph = *(uint32_t*)(g_hbh + (size_t)r * 128 + col);
                uint32_t pl = *(uint32_t*)(g_hbl + (size_t)r * 128 + col);
                float2 fh = __half22float2(*(__half2*)&ph);
                float2 fl = __half22float2(*(__half2*)&pl);
                float vx = fmaxf(acc[mt][nt][half_ * 2 + 0] + fh.x + fl.x + sB[col], 0.f);
                float vy = fmaxf(acc[mt][nt][half_ * 2 + 1] + fh.y + fl.y + sB[col + 1], 0.f);
                __half2 hp = __floats2half2_rn(vx, vy);
                *(uint32_t*)(outh + (size_t)r * 128 + col) = h2_bits(hp);
                float2 hr = __half22float2(hp);
                __half2 lp = __floats2half2_rn(vx - hr.x, vy - hr.y);
                *(uint32_t*)(outl + (size_t)r * 128 + col) = h2_bits(lp);
            }
        }
    }
}

// JK: relu(A1@s1 + A2@s2 + bias), plane store + pool
__global__ __launch_bounds__(256, 2) void k_gemmJK(
    const __half* __restrict__ A1h, const __half* __restrict__ A1l, int s1,
    const __half* __restrict__ A2h, const __half* __restrict__ A2l, int s2,
    const float* __restrict__ bias,
    __half* __restrict__ outh, __half* __restrict__ outl,
    const int* __restrict__ batch, int poolOff)
{
    extern __shared__ char smem[];
    uint32_t sb = smem_u32(smem);
    int tid = threadIdx.x, lane = tid & 31, wid = tid >> 5;
    int wm = (wid & 3) * 32, wn = (wid >> 2) * 64;
    int m0 = blockIdx.x * 128;
    float* sB = (float*)(smem + OFF_BI);
    if (tid < 128) sB[tid] = bias[tid];

    float acc[2][8][4];
    #pragma unroll
    for (int a = 0; a < 2; a++)
        #pragma unroll
        for (int b = 0; b < 8; b++)
            #pragma unroll
            for (int c = 0; c < 4; c++) acc[a][b][c] = 0.f;

    stage_direct(A1h, A1l, m0, tid, smem);
    panel_mma(acc, s1, smem, sb, tid, lane, wm, wn);
    __syncthreads();
    stage_direct(A2h, A2l, m0, tid, smem);
    panel_mma(acc, s2, smem, sb, tid, lane, wm, wn);

    epilogue(acc, sB, outh, outl, batch, poolOff, m0, lane, wm, wn);
}

// ---------------- head ----------------
__global__ void k_head(const float* __restrict__ gamma, const float* __restrict__ beta,
                       const float* __restrict__ rm, const float* __restrict__ rv,
                       const float* __restrict__ W1, const float* __restrict__ b1,
                       const float* __restrict__ W2, const float* __restrict__ b2,
                       float* __restrict__ out)
{
    __shared__ float sg[256];
    __shared__ float s1[128];
    __shared__ float s2[10];
    int gb = blockIdx.x, t = threadIdx.x;
    for (int i = t; i < 256; i += 128) {
        float v = g_pool[gb * 256 + i];
        v = (v - rm[i]) * rsqrtf(rv[i] + 1e-5f) * gamma[i] + beta[i];
        sg[i] = v;
    }
    __syncthreads();
    float acc = b1[t];
    #pragma unroll 8
    for (int k = 0; k < 256; k++) acc += sg[k] * W1[k * 128 + t];
    s1[t] = fmaxf(acc, 0.f);
    __syncthreads();
    if (t < 10) {
        float a = b2[t];
        #pragma unroll 8
        for (int k = 0; k < 128; k++) a += s1[k] * W2[k * 10 + t];
        s2[t] = a;
    }
    __syncthreads();
    if (t == 0) {
        float m = s2[0];
        for (int j = 1; j < 10; j++) m = fmaxf(m, s2[j]);
        float ex[10]; float sum = 0.f;
        for (int j = 0; j < 10; j++) { ex[j] = expf(s2[j] - m); sum += ex[j]; }
        float inv = 1.0f / sum;
        for (int j = 0; j < 10; j++) out[gb * 10 + j] = ex[j] * inv;
    }
}

// ---------------- host launch ----------------
extern "C" void kernel_launch(void* const* d_in, const int* in_sizes, int n_in,
                              void* d_out, int out_size)
{
    const float* x     = (const float*)d_in[0];
    const int*   ei    = (const int*)d_in[1];
    const int*   batch = (const int*)d_in[2];
    int base = (n_in > 3 && in_sizes[3] == 1) ? 4 : 3;

    const float* p[24];
    for (int i = 0; i < 24; i++) p[i] = (const float*)d_in[base + i];
    // b0: 0..7 (Wl1,Wr1,b1,Wl2,Wr2,b2,Wlin,blin); b1: 8..15; bn 16..19; lin1 20,21; lin2 22,23

    const int* src = ei;
    const int* dst = ei + EE;

    void *pxh, *pxl, *ph1h, *ph1l, *ph2h, *ph2l, *phch, *phcl;
    cudaGetSymbolAddress(&pxh,  g_xh);
    cudaGetSymbolAddress(&pxl,  g_xl);
    cudaGetSymbolAddress(&ph1h, g_h1h);
    cudaGetSymbolAddress(&ph1l, g_h1l);
    cudaGetSymbolAddress(&ph2h, g_h2h);
    cudaGetSymbolAddress(&ph2l, g_h2l);
    // block output planes reuse g_h2 for block1 conv2; block outputs:
    __half* xh  = (__half*)pxh;
    __half* xl  = (__half*)pxl;
    __half* h1h = (__half*)ph1h;
    __half* h1l = (__half*)ph1l;
    __half* h2h = (__half*)ph2h;
    __half* h2l = (__half*)ph2l;

    // dedicated block-output planes (reuse g_m? g_m is used for means) — use x planes
    // for block-0 output ONLY after x no longer needed: x IS needed as P2 input of
    // block0 conv1 only. After conv1, x planes are free -> block0 JK output goes there.
    __half* hbh = xh;
    __half* hbl = xl;

    cudaFuncSetAttribute(k_combo,  cudaFuncAttributeMaxDynamicSharedMemorySize, GEMM_SMEM);
    cudaFuncSetAttribute(k_gemm1,  cudaFuncAttributeMaxDynamicSharedMemorySize, GEMM_SMEM);
    cudaFuncSetAttribute(k_gemmJK, cudaFuncAttributeMaxDynamicSharedMemorySize, GEMM_SMEM);

    // ---- prep: zero; (count | x planes | W planes); scan; fill ----
    k_zero2<<<452, 256>>>();
    k_prep<<<13268, 256>>>(dst, x,
        p[0], p[1], p[3], p[4], p[6], p[6] + 16384,
        p[8], p[9], p[11], p[12], p[14], p[14] + 16384);
    k_scan<<<1, 1024>>>();
    k_fillcsr<<<(EE + 255) / 256, 256>>>(src, dst);

    const int COMBO_BLOCKS = 6250 + NGB;  // 6641

    // ---- block 0, conv1: agg(x) | x@Wr -> preact planes; then mean@Wl + preact ----
    k_combo<<<COMBO_BLOCKS, 256, GEMM_SMEM>>>(xh, xl, 0, 1, p[2], nullptr, nullptr);
    k_gemm1<<<NGB, 256, GEMM_SMEM>>>(0, p[2], h1h, h1l);
    // ---- block 0, conv2 ----
    k_combo<<<COMBO_BLOCKS, 256, GEMM_SMEM>>>(h1h, h1l, 2, 3, p[5], nullptr, nullptr);
    k_gemm1<<<NGB, 256, GEMM_SMEM>>>(2, p[5], h2h, h2l);
    // ---- block 0 JK + pool 0 (output into freed x planes) ----
    k_gemmJK<<<NGB, 256, GEMM_SMEM>>>(h1h, h1l, 4, h2h, h2l, 5, p[7], hbh, hbl, batch, 0);

    // ---- block 1, conv1 ----
    k_combo<<<COMBO_BLOCKS, 256, GEMM_SMEM>>>(hbh, hbl, 6, 7, p[10], nullptr, nullptr);
    k_gemm1<<<NGB, 256, GEMM_SMEM>>>(6, p[10], h1h, h1l);
    // ---- block 1, conv2 ----
    k_combo<<<COMBO_BLOCKS, 256, GEMM_SMEM>>>(h1h, h1l, 8, 9, p[13], nullptr, nullptr);
    k_gemm1<<<NGB, 256, GEMM_SMEM>>>(8, p[13], h2h, h2l);
    // ---- block 1 JK + pool 1 (no plane store needed, but reuse path; pool only) ----
    k_gemmJK<<<NGB, 256, GEMM_SMEM>>>(h1h, h1l, 10, h2h, h2l, 11, p[15],
                                      nullptr, nullptr, batch, 128);

    // ---- head ----
    k_head<<<GG, 128>>>(p[16], p[17], p[18], p[19], p[20], p[21], p[22], p[23],
                        (float*)d_out);
}

// round 11
// speedup vs baseline: 1.2297x; 1.0758x over previous
#include <cuda_runtime.h>
#include <cuda_fp16.h>
#include <cstdint>
#include <math.h>

#define NN 50000
#define EE 1600000
#define GG 256
#define HH 128
#define NGB 391   // ceil(50000/128)

// ---------------- scratch ----------------
__device__ int   g_row[NN + 1];
__device__ int   g_col[EE];
__device__ int   g_fill[NN];
__device__ float g_deginv[NN];
__device__ float g_pool[GG * 2 * HH];
// fp16 hi/lo activation planes
__device__ __align__(16) __half g_xh[NN * HH], g_xl[NN * HH];
__device__ __align__(16) __half g_mh[NN * HH], g_ml[NN * HH];
__device__ __align__(16) __half g_h1h[NN * HH], g_h1l[NN * HH];
__device__ __align__(16) __half g_h2h[NN * HH], g_h2l[NN * HH];
__device__ __align__(16) __half g_hbh[NN * HH], g_hbl[NN * HH];
// 12 weight slots of 128x128, fp16 (hi only — 2-term scheme)
__device__ __align__(16) __half g_Wh[12 * 16384];

__device__ __forceinline__ uint32_t smem_u32(const void* p) {
    uint32_t a;
    asm("{ .reg .u64 t; cvta.to.shared.u64 t, %1; cvt.u32.u64 %0, t; }" : "=r"(a) : "l"(p));
    return a;
}
__device__ __forceinline__ uint32_t h2_bits(__half2 h) { return *(uint32_t*)&h; }

// ---------------- prep kernels ----------------
// runs at TAIL of each call (globals are zero-initialized at load, so call 1 is fine)
__global__ void k_zero2() {
    int b = blockIdx.x;
    if (b < 196) {
        int i = b * 256 + threadIdx.x;
        if (i < NN) g_fill[i] = 0;
    } else {
        int i = (b - 196) * 256 + threadIdx.x;
        if (i < GG * 256) g_pool[i] = 0.f;
    }
}

// merged: degree count | x->planes | W->fp16
__global__ void k_prep(const int* __restrict__ dst, const float* __restrict__ x,
                       const float* s0, const float* s1, const float* s2, const float* s3,
                       const float* s4, const float* s5, const float* s6, const float* s7,
                       const float* s8, const float* s9, const float* s10, const float* s11)
{
    int b = blockIdx.x;
    if (b < 6250) {
        int e = b * 256 + threadIdx.x;
        atomicAdd(&g_fill[dst[e]], 1);
    } else if (b < 12500) {
        int i = ((b - 6250) * 256 + threadIdx.x) * 4;
        float4 v = *(const float4*)(x + i);
        __half2 h01 = __floats2half2_rn(v.x, v.y);
        __half2 h23 = __floats2half2_rn(v.z, v.w);
        *(uint2*)(g_xh + i) = make_uint2(h2_bits(h01), h2_bits(h23));
        float2 r01 = __half22float2(h01);
        float2 r23 = __half22float2(h23);
        __half2 l01 = __floats2half2_rn(v.x - r01.x, v.y - r01.y);
        __half2 l23 = __floats2half2_rn(v.z - r23.x, v.w - r23.y);
        *(uint2*)(g_xl + i) = make_uint2(h2_bits(l01), h2_bits(l23));
    } else {
        int idx = (b - 12500) * 256 + threadIdx.x;   // 12*16384
        int slot = idx >> 14;
        int w = idx & 16383;
        const float* src;
        switch (slot) {
            case 0: src = s0; break; case 1: src = s1; break;
            case 2: src = s2; break; case 3: src = s3; break;
            case 4: src = s4; break; case 5: src = s5; break;
            case 6: src = s6; break; case 7: src = s7; break;
            case 8: src = s8; break; case 9: src = s9; break;
            case 10: src = s10; break; default: src = s11; break;
        }
        g_Wh[idx] = __float2half_rn(src[w]);
    }
}

__global__ void k_scan() {
    __shared__ int ssum[1024];
    int t = threadIdx.x;
    const int C = (NN + 1023) / 1024;
    int s = t * C;
    int e = s + C; if (e > NN) e = NN;
    int loc = 0;
    for (int i = s; i < e; i++) loc += g_fill[i];
    ssum[t] = loc;
    __syncthreads();
    if (t == 0) {
        int run = 0;
        for (int i = 0; i < 1024; i++) { int v = ssum[i]; ssum[i] = run; run += v; }
        g_row[NN] = run;
    }
    __syncthreads();
    int run = ssum[t];
    for (int i = s; i < e; i++) {
        int c = g_fill[i];
        g_row[i]    = run;
        g_fill[i]   = run;
        g_deginv[i] = 1.0f / fmaxf((float)c, 1.0f);
        run += c;
    }
}
__global__ void k_fillcsr(const int* __restrict__ src, const int* __restrict__ dst) {
    int e = blockIdx.x * blockDim.x + threadIdx.x;
    if (e < EE) {
        int pos = atomicAdd(&g_fill[dst[e]], 1);
        g_col[pos] = src[e];
    }
}

// ---------------- GEMM helpers ----------------
// SMEM: Ah 32KB | Al 32KB | Wh 16KB | bias
static constexpr int OFF_AH = 0;
static constexpr int OFF_AL = 32768;
static constexpr int OFF_WH = 65536;
static constexpr int OFF_BI = 81920;
static constexpr int GEMM_SMEM = 82432;

__device__ __forceinline__ uint32_t swz(uint32_t row, uint32_t kbyte) {
    uint32_t col16 = kbyte >> 4;
    uint32_t scol = col16 ^ (row & 7);
    return row * 256 + scol * 16 + (kbyte & 15);
}
__device__ __forceinline__ void ldsm_x4(uint32_t* r, uint32_t addr) {
    asm volatile("ldmatrix.sync.aligned.m8n8.x4.shared.b16 {%0,%1,%2,%3}, [%4];"
                 : "=r"(r[0]), "=r"(r[1]), "=r"(r[2]), "=r"(r[3]) : "r"(addr));
}
__device__ __forceinline__ void ldsm_x4_t(uint32_t* r, uint32_t addr) {
    asm volatile("ldmatrix.sync.aligned.m8n8.x4.trans.shared.b16 {%0,%1,%2,%3}, [%4];"
                 : "=r"(r[0]), "=r"(r[1]), "=r"(r[2]), "=r"(r[3]) : "r"(addr));
}
__device__ __forceinline__ void mma16816(float* c, const uint32_t* a, uint32_t b0, uint32_t b1) {
    asm volatile(
        "mma.sync.aligned.m16n8k16.row.col.f32.f16.f16.f32 "
        "{%0,%1,%2,%3}, {%4,%5,%6,%7}, {%8,%9}, {%0,%1,%2,%3};"
        : "+f"(c[0]), "+f"(c[1]), "+f"(c[2]), "+f"(c[3])
        : "r"(a[0]), "r"(a[1]), "r"(a[2]), "r"(a[3]), "r"(b0), "r"(b1));
}

// one panel, 2-term: (Ah + Al) @ Wh over K=128 from resident A planes
__device__ __forceinline__ void panel_mma(
    float acc[2][8][4], int slot, char* smem, uint32_t sb,
    int tid, int lane, int wm, int wn)
{
    const __half* wh = g_Wh + slot * 16384;
    uint32_t aRow = (uint32_t)(wm + (lane & 15));
    uint32_t aKadd = (uint32_t)((lane >> 4) * 16);
    uint32_t wRowL = (uint32_t)(lane & 15);
    uint32_t nAdd = (uint32_t)((lane >> 4) * 16);
    int k = tid >> 2, q4 = tid & 3;

    #pragma unroll
    for (int c = 0; c < 2; c++) {
        __syncthreads();   // A visible / prev W consumed
        {
            const uint4* whp = (const uint4*)(wh + (size_t)(c * 64 + k) * 128 + q4 * 32);
            #pragma unroll
            for (int q = 0; q < 4; q++) {
                uint32_t b = (uint32_t)(q4 * 64 + q * 16);
                *(uint4*)(smem + OFF_WH + swz((uint32_t)k, b)) = whp[q];
            }
        }
        __syncthreads();
        #pragma unroll
        for (int ks = 0; ks < 4; ks++) {
            uint32_t kb = (uint32_t)(c * 128 + ks * 32) + aKadd;
            uint32_t ah0[4], ah1[4], al0[4], al1[4];
            ldsm_x4(ah0, sb + OFF_AH + swz(aRow, kb));
            ldsm_x4(ah1, sb + OFF_AH + swz(aRow + 16, kb));
            ldsm_x4(al0, sb + OFF_AL + swz(aRow, kb));
            ldsm_x4(al1, sb + OFF_AL + swz(aRow + 16, kb));
            uint32_t wRow = (uint32_t)(ks * 16) + wRowL;
            #pragma unroll
            for (int bt = 0; bt < 4; bt++) {
                uint32_t nb = (uint32_t)((wn + bt * 16) * 2) + nAdd;
                uint32_t bh[4];
                ldsm_x4_t(bh, sb + OFF_WH + swz(wRow, nb));
                mma16816(acc[0][bt * 2 + 0], ah0, bh[0], bh[1]);
                mma16816(acc[0][bt * 2 + 1], ah0, bh[2], bh[3]);
                mma16816(acc[1][bt * 2 + 0], ah1, bh[0], bh[1]);
                mma16816(acc[1][bt * 2 + 1], ah1, bh[2], bh[3]);
                mma16816(acc[0][bt * 2 + 0], al0, bh[0], bh[1]);
                mma16816(acc[0][bt * 2 + 1], al0, bh[2], bh[3]);
                mma16816(acc[1][bt * 2 + 0], al1, bh[0], bh[1]);
                mma16816(acc[1][bt * 2 + 1], al1, bh[2], bh[3]);
            }
        }
    }
}

// stage direct plane rows into SMEM A (full K=128)
__device__ __forceinline__ void stage_direct(
    const __half* Ah, const __half* Al,
    int m0, int tid, char* smem)
{
    int r = tid >> 1, half_ = tid & 1;
    int gr = m0 + r; if (gr > NN - 1) gr = NN - 1;
    size_t gofs = (size_t)gr * 128 + half_ * 64;
    const uint4* aph = (const uint4*)(Ah + gofs);
    const uint4* apl = (const uint4*)(Al + gofs);
    #pragma unroll
    for (int q = 0; q < 8; q++) {
        uint32_t kb = (uint32_t)(half_ * 128 + q * 16);
        uint32_t so = swz((uint32_t)r, kb);
        *(uint4*)(smem + OFF_AH + so) = aph[q];
        *(uint4*)(smem + OFF_AL + so) = apl[q];
    }
}

// epilogue: bias+relu; plane store and/or pool
__device__ __forceinline__ void epilogue(
    float acc[2][8][4], const float* sB,
    __half* outh, __half* outl,
    const int* batch, int poolOff,
    int m0, int lane, int wm, int wn)
{
    int g = lane >> 2, tg = lane & 3;
    #pragma unroll
    for (int mt = 0; mt < 2; mt++) {
        #pragma unroll
        for (int half_ = 0; half_ < 2; half_++) {
            int r = m0 + wm + mt * 16 + g + half_ * 8;
            if (r >= NN) continue;
            int bi = batch ? batch[r] : 0;
            #pragma unroll
            for (int nt = 0; nt < 8; nt++) {
                int col = wn + nt * 8 + tg * 2;
                float vx = fmaxf(acc[mt][nt][half_ * 2 + 0] + sB[col], 0.f);
                float vy = fmaxf(acc[mt][nt][half_ * 2 + 1] + sB[col + 1], 0.f);
                if (outh) {
                    __half2 hp = __floats2half2_rn(vx, vy);
                    *(uint32_t*)(outh + (size_t)r * 128 + col) = h2_bits(hp);
                    float2 hr = __half22float2(hp);
                    __half2 lp = __floats2half2_rn(vx - hr.x, vy - hr.y);
                    *(uint32_t*)(outl + (size_t)r * 128 + col) = h2_bits(lp);
                }
                if (batch) {
                    float* pp = g_pool + (size_t)bi * 256 + poolOff + col;
                    atomicAdd(pp + 0, vx);
                    atomicAdd(pp + 1, vy);
                }
            }
        }
    }
}

// ---------------- co-scheduled kernel: agg blocks + P2 GEMM blocks ----------------
// gemm blocks at bid % 17 == 0 (391); rest are agg blocks (6250).
// agg gathers the hi plane only (256B/edge); mean stored as fp16 hi/lo.
__global__ __launch_bounds__(256, 2) void k_combo(
    const __half* __restrict__ inh, const __half* __restrict__ inl,
    int slotL, int slotR, const float* __restrict__ bias)
{
    extern __shared__ char smem[];
    int bid = blockIdx.x;
    int g17 = bid / 17, r17 = bid % 17;
    int tid = threadIdx.x, lane = tid & 31, wid = tid >> 5;

    if (r17 == 0 && g17 < NGB) {
        // ---- P2 GEMM block: preact = in @ Wr, stored as fp16 hi/lo planes ----
        uint32_t sb = smem_u32(smem);
        int wm = (wid & 3) * 32, wn = (wid >> 2) * 64;
        int m0 = g17 * 128;
        float acc[2][8][4];
        #pragma unroll
        for (int a = 0; a < 2; a++)
            #pragma unroll
            for (int b = 0; b < 8; b++)
                #pragma unroll
                for (int c = 0; c < 4; c++) acc[a][b][c] = 0.f;
        stage_direct(inh, inl, m0, tid, smem);
        panel_mma(acc, slotR, smem, sb, tid, lane, wm, wn);
        int g = lane >> 2, tg = lane & 3;
        #pragma unroll
        for (int mt = 0; mt < 2; mt++) {
            #pragma unroll
            for (int half_ = 0; half_ < 2; half_++) {
                int r = m0 + wm + mt * 16 + g + half_ * 8;
                if (r >= NN) continue;
                #pragma unroll
                for (int nt = 0; nt < 8; nt++) {
                    int col = wn + nt * 8 + tg * 2;
                    float vx = acc[mt][nt][half_ * 2 + 0];
                    float vy = acc[mt][nt][half_ * 2 + 1];
                    __half2 hp = __floats2half2_rn(vx, vy);
                    *(uint32_t*)(g_hbh + (size_t)r * 128 + col) = h2_bits(hp);
                    float2 hr = __half22float2(hp);
                    __half2 lp = __floats2half2_rn(vx - hr.x, vy - hr.y);
                    *(uint32_t*)(g_hbl + (size_t)r * 128 + col) = h2_bits(lp);
                }
            }
        }
    } else {
        int pre = g17 + 1; if (pre > NGB) pre = NGB;
        int aid = bid - pre;
        int n = aid * 8 + wid;
        if (n >= NN) return;
        int s = g_row[n], e = g_row[n + 1];
        float a0 = 0.f, a1 = 0.f, a2 = 0.f, a3 = 0.f;
        const __half* bh = inh + lane * 4;
        #pragma unroll 8
        for (int i = s; i < e; i++) {
            int cc = __ldg(&g_col[i]);
            uint2 uh = *(const uint2*)(bh + (size_t)cc * HH);
            float2 f0 = __half22float2(*(__half2*)&uh.x);
            float2 f1 = __half22float2(*(__half2*)&uh.y);
            a0 += f0.x; a1 += f0.y; a2 += f1.x; a3 += f1.y;
        }
        float d = g_deginv[n];
        a0 *= d; a1 *= d; a2 *= d; a3 *= d;
        __half2 hp0 = __floats2half2_rn(a0, a1);
        __half2 hp1 = __floats2half2_rn(a2, a3);
        *(uint2*)(g_mh + (size_t)n * HH + lane * 4) =
            make_uint2(h2_bits(hp0), h2_bits(hp1));
        float2 r0 = __half22float2(hp0);
        float2 r1 = __half22float2(hp1);
        __half2 lp0 = __floats2half2_rn(a0 - r0.x, a1 - r0.y);
        __half2 lp1 = __floats2half2_rn(a2 - r1.x, a3 - r1.y);
        *(uint2*)(g_ml + (size_t)n * HH + lane * 4) =
            make_uint2(h2_bits(lp0), h2_bits(lp1));
    }
}

// single-panel GEMM: out = relu(mean@slot + preact planes + bias), plane output
__global__ __launch_bounds__(256, 2) void k_gemm1(
    int slotL, const float* __restrict__ bias,
    __half* __restrict__ outh, __half* __restrict__ outl)
{
    extern __shared__ char smem[];
    uint32_t sb = smem_u32(smem);
    int tid = threadIdx.x, lane = tid & 31, wid = tid >> 5;
    int wm = (wid & 3) * 32, wn = (wid >> 2) * 64;
    int m0 = blockIdx.x * 128;
    float* sB = (float*)(smem + OFF_BI);
    if (tid < 128) sB[tid] = bias[tid];

    float acc[2][8][4];
    #pragma unroll
    for (int a = 0; a < 2; a++)
        #pragma unroll
        for (int b = 0; b < 8; b++)
            #pragma unroll
            for (int c = 0; c < 4; c++) acc[a][b][c] = 0.f;

    stage_direct(g_mh, g_ml, m0, tid, smem);
    panel_mma(acc, slotL, smem, sb, tid, lane, wm, wn);

    int g = lane >> 2, tg = lane & 3;
    #pragma unroll
    for (int mt = 0; mt < 2; mt++) {
        #pragma unroll
        for (int half_ = 0; half_ < 2; half_++) {
            int r = m0 + wm + mt * 16 + g + half_ * 8;
            if (r >= NN) continue;
            #pragma unroll
            for (int nt = 0; nt < 8; nt++) {
                int col = wn + nt * 8 + tg * 2;
                uint32_t ph = *(uint32_t*)(g_hbh + (size_t)r * 128 + col);
                uint32_t pl = *(uint32_t*)(g_hbl + (size_t)r * 128 + col);
                float2 fh = __half22float2(*(__half2*)&ph);
                float2 fl = __half22float2(*(__half2*)&pl);
                float vx = fmaxf(acc[mt][nt][half_ * 2 + 0] + fh.x + fl.x + sB[col], 0.f);
                float vy = fmaxf(acc[mt][nt][half_ * 2 + 1] + fh.y + fl.y + sB[col + 1], 0.f);
                __half2 hp = __floats2half2_rn(vx, vy);
                *(uint32_t*)(outh + (size_t)r * 128 + col) = h2_bits(hp);
                float2 hr = __half22float2(hp);
                __half2 lp = __floats2half2_rn(vx - hr.x, vy - hr.y);
                *(uint32_t*)(outl + (size_t)r * 128 + col) = h2_bits(lp);
            }
        }
    }
}

// JK: relu(A1@s1 + A2@s2 + bias), plane store + pool
__global__ __launch_bounds__(256, 2) void k_gemmJK(
    const __half* __restrict__ A1h, const __half* __restrict__ A1l, int s1,
    const __half* __restrict__ A2h, const __half* __restrict__ A2l, int s2,
    const float* __restrict__ bias,
    __half* __restrict__ outh, __half* __restrict__ outl,
    const int* __restrict__ batch, int poolOff)
{
    extern __shared__ char smem[];
    uint32_t sb = smem_u32(smem);
    int tid = threadIdx.x, lane = tid & 31, wid = tid >> 5;
    int wm = (wid & 3) * 32, wn = (wid >> 2) * 64;
    int m0 = blockIdx.x * 128;
    float* sB = (float*)(smem + OFF_BI);
    if (tid < 128) sB[tid] = bias[tid];

    float acc[2][8][4];
    #pragma unroll
    for (int a = 0; a < 2; a++)
        #pragma unroll
        for (int b = 0; b < 8; b++)
            #pragma unroll
            for (int c = 0; c < 4; c++) acc[a][b][c] = 0.f;

    stage_direct(A1h, A1l, m0, tid, smem);
    panel_mma(acc, s1, smem, sb, tid, lane, wm, wn);
    __syncthreads();
    stage_direct(A2h, A2l, m0, tid, smem);
    panel_mma(acc, s2, smem, sb, tid, lane, wm, wn);

    epilogue(acc, sB, outh, outl, batch, poolOff, m0, lane, wm, wn);
}

// ---------------- head ----------------
__global__ void k_head(const float* __restrict__ gamma, const float* __restrict__ beta,
                       const float* __restrict__ rm, const float* __restrict__ rv,
                       const float* __restrict__ W1, const float* __restrict__ b1,
                       const float* __restrict__ W2, const float* __restrict__ b2,
                       float* __restrict__ out)
{
    __shared__ float sg[256];
    __shared__ float s1[128];
    __shared__ float s2[10];
    int gb = blockIdx.x, t = threadIdx.x;
    for (int i = t; i < 256; i += 128) {
        float v = g_pool[gb * 256 + i];
        v = (v - rm[i]) * rsqrtf(rv[i] + 1e-5f) * gamma[i] + beta[i];
        sg[i] = v;
    }
    __syncthreads();
    float acc = b1[t];
    #pragma unroll 8
    for (int k = 0; k < 256; k++) acc += sg[k] * W1[k * 128 + t];
    s1[t] = fmaxf(acc, 0.f);
    __syncthreads();
    if (t < 10) {
        float a = b2[t];
        #pragma unroll 8
        for (int k = 0; k < 128; k++) a += s1[k] * W2[k * 10 + t];
        s2[t] = a;
    }
    __syncthreads();
    if (t == 0) {
        float m = s2[0];
        for (int j = 1; j < 10; j++) m = fmaxf(m, s2[j]);
        float ex[10]; float sum = 0.f;
        for (int j = 0; j < 10; j++) { ex[j] = expf(s2[j] - m); sum += ex[j]; }
        float inv = 1.0f / sum;
        for (int j = 0; j < 10; j++) out[gb * 10 + j] = ex[j] * inv;
    }
}

// ---------------- host launch ----------------
extern "C" void kernel_launch(void* const* d_in, const int* in_sizes, int n_in,
                              void* d_out, int out_size)
{
    const float* x     = (const float*)d_in[0];
    const int*   ei    = (const int*)d_in[1];
    const int*   batch = (const int*)d_in[2];
    int base = (n_in > 3 && in_sizes[3] == 1) ? 4 : 3;

    const float* p[24];
    for (int i = 0; i < 24; i++) p[i] = (const float*)d_in[base + i];
    // b0: 0..7 (Wl1,Wr1,b1,Wl2,Wr2,b2,Wlin,blin); b1: 8..15; bn 16..19; lin1 20,21; lin2 22,23

    const int* src = ei;
    const int* dst = ei + EE;

    void *pxh, *pxl, *ph1h, *ph1l, *ph2h, *ph2l;
    cudaGetSymbolAddress(&pxh,  g_xh);
    cudaGetSymbolAddress(&pxl,  g_xl);
    cudaGetSymbolAddress(&ph1h, g_h1h);
    cudaGetSymbolAddress(&ph1l, g_h1l);
    cudaGetSymbolAddress(&ph2h, g_h2h);
    cudaGetSymbolAddress(&ph2l, g_h2l);

    __half* xh  = (__half*)pxh;
    __half* xl  = (__half*)pxl;
    __half* h1h = (__half*)ph1h;
    __half* h1l = (__half*)ph1l;
    __half* h2h = (__half*)ph2h;
    __half* h2l = (__half*)ph2l;

    // x planes freed after block-0 conv1 -> reuse as block-0 output (hb)
    __half* hbh = xh;
    __half* hbl = xl;

    cudaFuncSetAttribute(k_combo,  cudaFuncAttributeMaxDynamicSharedMemorySize, GEMM_SMEM);
    cudaFuncSetAttribute(k_gemm1,  cudaFuncAttributeMaxDynamicSharedMemorySize, GEMM_SMEM);
    cudaFuncSetAttribute(k_gemmJK, cudaFuncAttributeMaxDynamicSharedMemorySize, GEMM_SMEM);

    // ---- prep (g_fill/g_pool were zeroed by the tail of the previous call;
    //      zero-initialized at module load for call 1) ----
    k_prep<<<13268, 256>>>(dst, x,
        p[0], p[1], p[3], p[4], p[6], p[6] + 16384,
        p[8], p[9], p[11], p[12], p[14], p[14] + 16384);
    k_scan<<<1, 1024>>>();
    k_fillcsr<<<(EE + 255) / 256, 256>>>(src, dst);

    const int COMBO_BLOCKS = 6250 + NGB;  // 6641

    // ---- block 0, conv1 ----
    k_combo<<<COMBO_BLOCKS, 256, GEMM_SMEM>>>(xh, xl, 0, 1, p[2]);
    k_gemm1<<<NGB, 256, GEMM_SMEM>>>(0, p[2], h1h, h1l);
    // ---- block 0, conv2 ----
    k_combo<<<COMBO_BLOCKS, 256, GEMM_SMEM>>>(h1h, h1l, 2, 3, p[5]);
    k_gemm1<<<NGB, 256, GEMM_SMEM>>>(2, p[5], h2h, h2l);
    // ---- block 0 JK + pool 0 (output into freed x planes) ----
    k_gemmJK<<<NGB, 256, GEMM_SMEM>>>(h1h, h1l, 4, h2h, h2l, 5, p[7], hbh, hbl, batch, 0);

    // ---- block 1, conv1 ----
    k_combo<<<COMBO_BLOCKS, 256, GEMM_SMEM>>>(hbh, hbl, 6, 7, p[10]);
    k_gemm1<<<NGB, 256, GEMM_SMEM>>>(6, p[10], h1h, h1l);
    // ---- block 1, conv2 ----
    k_combo<<<COMBO_BLOCKS, 256, GEMM_SMEM>>>(h1h, h1l, 8, 9, p[13]);
    k_gemm1<<<NGB, 256, GEMM_SMEM>>>(8, p[13], h2h, h2l);
    // ---- block 1 JK + pool 1 (pool only) ----
    k_gemmJK<<<NGB, 256, GEMM_SMEM>>>(h1h, h1l, 10, h2h, h2l, 11, p[15],
                                      nullptr, nullptr, batch, 128);

    // ---- head ----
    k_head<<<GG, 128>>>(p[16], p[17], p[18], p[19], p[20], p[21], p[22], p[23],
                        (float*)d_out);

    // ---- tail: restore zeroed state for the next call ----
    k_zero2<<<452, 256>>>();
}

// round 12
// speedup vs baseline: 1.8232x; 1.4826x over previous
#include <cuda_runtime.h>
#include <cuda_fp16.h>
#include <cstdint>
#include <math.h>

#define NN 50000
#define EE 1600000
#define GG 256
#define HH 128
#define NGB 391   // ceil(50000/128)

// ---------------- scratch ----------------
__device__ int   g_row[NN + 1];
__device__ int   g_col[EE];
__device__ int   g_fill[NN];
__device__ float g_deginv[NN];
__device__ float g_pool[GG * 2 * HH];
// fp16 hi/lo activation planes
__device__ __align__(16) __half g_xh[NN * HH], g_xl[NN * HH];
__device__ __align__(16) __half g_mh[NN * HH], g_ml[NN * HH];
__device__ __align__(16) __half g_h1h[NN * HH], g_h1l[NN * HH];
__device__ __align__(16) __half g_h2h[NN * HH], g_h2l[NN * HH];
// 12 weight slots of 128x128, fp16 (hi only — 2-term scheme)
__device__ __align__(16) __half g_Wh[12 * 16384];

__device__ __forceinline__ uint32_t smem_u32(const void* p) {
    uint32_t a;
    asm("{ .reg .u64 t; cvta.to.shared.u64 t, %1; cvt.u32.u64 %0, t; }" : "=r"(a) : "l"(p));
    return a;
}
__device__ __forceinline__ uint32_t h2_bits(__half2 h) { return *(uint32_t*)&h; }

// ---------------- prep kernels ----------------
// runs at TAIL of each call (globals zero-initialized at load, so call 1 is fine)
__global__ void k_zero2() {
    int b = blockIdx.x;
    if (b < 196) {
        int i = b * 256 + threadIdx.x;
        if (i < NN) g_fill[i] = 0;
    } else {
        int i = (b - 196) * 256 + threadIdx.x;
        if (i < GG * 256) g_pool[i] = 0.f;
    }
}

// merged: degree count | x->planes | W->fp16
__global__ void k_prep(const int* __restrict__ dst, const float* __restrict__ x,
                       const float* s0, const float* s1, const float* s2, const float* s3,
                       const float* s4, const float* s5, const float* s6, const float* s7,
                       const float* s8, const float* s9, const float* s10, const float* s11)
{
    int b = blockIdx.x;
    if (b < 6250) {
        int e = b * 256 + threadIdx.x;
        atomicAdd(&g_fill[dst[e]], 1);
    } else if (b < 12500) {
        int i = ((b - 6250) * 256 + threadIdx.x) * 4;
        float4 v = *(const float4*)(x + i);
        __half2 h01 = __floats2half2_rn(v.x, v.y);
        __half2 h23 = __floats2half2_rn(v.z, v.w);
        *(uint2*)(g_xh + i) = make_uint2(h2_bits(h01), h2_bits(h23));
        float2 r01 = __half22float2(h01);
        float2 r23 = __half22float2(h23);
        __half2 l01 = __floats2half2_rn(v.x - r01.x, v.y - r01.y);
        __half2 l23 = __floats2half2_rn(v.z - r23.x, v.w - r23.y);
        *(uint2*)(g_xl + i) = make_uint2(h2_bits(l01), h2_bits(l23));
    } else {
        int idx = (b - 12500) * 256 + threadIdx.x;   // 12*16384
        int slot = idx >> 14;
        int w = idx & 16383;
        const float* src;
        switch (slot) {
            case 0: src = s0; break; case 1: src = s1; break;
            case 2: src = s2; break; case 3: src = s3; break;
            case 4: src = s4; break; case 5: src = s5; break;
            case 6: src = s6; break; case 7: src = s7; break;
            case 8: src = s8; break; case 9: src = s9; break;
            case 10: src = s10; break; default: src = s11; break;
        }
        g_Wh[idx] = __float2half_rn(src[w]);
    }
}

__global__ void k_scan() {
    __shared__ int ssum[1024];
    int t = threadIdx.x;
    const int C = (NN + 1023) / 1024;
    int s = t * C;
    int e = s + C; if (e > NN) e = NN;
    int loc = 0;
    for (int i = s; i < e; i++) loc += g_fill[i];
    ssum[t] = loc;
    __syncthreads();
    if (t == 0) {
        int run = 0;
        for (int i = 0; i < 1024; i++) { int v = ssum[i]; ssum[i] = run; run += v; }
        g_row[NN] = run;
    }
    __syncthreads();
    int run = ssum[t];
    for (int i = s; i < e; i++) {
        int c = g_fill[i];
        g_row[i]    = run;
        g_fill[i]   = run;
        g_deginv[i] = 1.0f / fmaxf((float)c, 1.0f);
        run += c;
    }
}
__global__ void k_fillcsr(const int* __restrict__ src, const int* __restrict__ dst) {
    int e = blockIdx.x * blockDim.x + threadIdx.x;
    if (e < EE) {
        int pos = atomicAdd(&g_fill[dst[e]], 1);
        g_col[pos] = src[e];
    }
}

// ---------------- standalone aggregation (zero smem, high occupancy) ----------------
// one warp per node; gathers hi plane only (256B/node-row), writes mean hi/lo planes.
__global__ __launch_bounds__(256) void k_agg(const __half* __restrict__ inh) {
    int wid = threadIdx.x >> 5, lane = threadIdx.x & 31;
    int n = blockIdx.x * 8 + wid;
    if (n >= NN) return;
    int s = g_row[n], e = g_row[n + 1];
    float a0 = 0.f, a1 = 0.f, a2 = 0.f, a3 = 0.f;
    const __half* bh = inh + lane * 4;
    #pragma unroll 8
    for (int i = s; i < e; i++) {
        int cc = __ldg(&g_col[i]);
        uint2 uh = *(const uint2*)(bh + (size_t)cc * HH);
        float2 f0 = __half22float2(*(__half2*)&uh.x);
        float2 f1 = __half22float2(*(__half2*)&uh.y);
        a0 += f0.x; a1 += f0.y; a2 += f1.x; a3 += f1.y;
    }
    float d = g_deginv[n];
    a0 *= d; a1 *= d; a2 *= d; a3 *= d;
    __half2 hp0 = __floats2half2_rn(a0, a1);
    __half2 hp1 = __floats2half2_rn(a2, a3);
    *(uint2*)(g_mh + (size_t)n * HH + lane * 4) =
        make_uint2(h2_bits(hp0), h2_bits(hp1));
    float2 r0 = __half22float2(hp0);
    float2 r1 = __half22float2(hp1);
    __half2 lp0 = __floats2half2_rn(a0 - r0.x, a1 - r0.y);
    __half2 lp1 = __floats2half2_rn(a2 - r1.x, a3 - r1.y);
    *(uint2*)(g_ml + (size_t)n * HH + lane * 4) =
        make_uint2(h2_bits(lp0), h2_bits(lp1));
}

// ---------------- GEMM helpers ----------------
// SMEM: Ah 32KB | Al 32KB | Wh 16KB | bias
static constexpr int OFF_AH = 0;
static constexpr int OFF_AL = 32768;
static constexpr int OFF_WH = 65536;
static constexpr int OFF_BI = 81920;
static constexpr int GEMM_SMEM = 82432;

__device__ __forceinline__ uint32_t swz(uint32_t row, uint32_t kbyte) {
    uint32_t col16 = kbyte >> 4;
    uint32_t scol = col16 ^ (row & 7);
    return row * 256 + scol * 16 + (kbyte & 15);
}
__device__ __forceinline__ void ldsm_x4(uint32_t* r, uint32_t addr) {
    asm volatile("ldmatrix.sync.aligned.m8n8.x4.shared.b16 {%0,%1,%2,%3}, [%4];"
                 : "=r"(r[0]), "=r"(r[1]), "=r"(r[2]), "=r"(r[3]) : "r"(addr));
}
__device__ __forceinline__ void ldsm_x4_t(uint32_t* r, uint32_t addr) {
    asm volatile("ldmatrix.sync.aligned.m8n8.x4.trans.shared.b16 {%0,%1,%2,%3}, [%4];"
                 : "=r"(r[0]), "=r"(r[1]), "=r"(r[2]), "=r"(r[3]) : "r"(addr));
}
__device__ __forceinline__ void mma16816(float* c, const uint32_t* a, uint32_t b0, uint32_t b1) {
    asm volatile(
        "mma.sync.aligned.m16n8k16.row.col.f32.f16.f16.f32 "
        "{%0,%1,%2,%3}, {%4,%5,%6,%7}, {%8,%9}, {%0,%1,%2,%3};"
        : "+f"(c[0]), "+f"(c[1]), "+f"(c[2]), "+f"(c[3])
        : "r"(a[0]), "r"(a[1]), "r"(a[2]), "r"(a[3]), "r"(b0), "r"(b1));
}

// one panel, 2-term: (Ah + Al) @ Wh over K=128 from resident A planes
__device__ __forceinline__ void panel_mma(
    float acc[2][8][4], int slot, char* smem, uint32_t sb,
    int tid, int lane, int wm, int wn)
{
    const __half* wh = g_Wh + slot * 16384;
    uint32_t aRow = (uint32_t)(wm + (lane & 15));
    uint32_t aKadd = (uint32_t)((lane >> 4) * 16);
    uint32_t wRowL = (uint32_t)(lane & 15);
    uint32_t nAdd = (uint32_t)((lane >> 4) * 16);
    int k = tid >> 2, q4 = tid & 3;

    #pragma unroll
    for (int c = 0; c < 2; c++) {
        __syncthreads();   // A visible / prev W consumed
        {
            const uint4* whp = (const uint4*)(wh + (size_t)(c * 64 + k) * 128 + q4 * 32);
            #pragma unroll
            for (int q = 0; q < 4; q++) {
                uint32_t b = (uint32_t)(q4 * 64 + q * 16);
                *(uint4*)(smem + OFF_WH + swz((uint32_t)k, b)) = whp[q];
            }
        }
        __syncthreads();
        #pragma unroll
        for (int ks = 0; ks < 4; ks++) {
            uint32_t kb = (uint32_t)(c * 128 + ks * 32) + aKadd;
            uint32_t ah0[4], ah1[4], al0[4], al1[4];
            ldsm_x4(ah0, sb + OFF_AH + swz(aRow, kb));
            ldsm_x4(ah1, sb + OFF_AH + swz(aRow + 16, kb));
            ldsm_x4(al0, sb + OFF_AL + swz(aRow, kb));
            ldsm_x4(al1, sb + OFF_AL + swz(aRow + 16, kb));
            uint32_t wRow = (uint32_t)(ks * 16) + wRowL;
            #pragma unroll
            for (int bt = 0; bt < 4; bt++) {
                uint32_t nb = (uint32_t)((wn + bt * 16) * 2) + nAdd;
                uint32_t bh[4];
                ldsm_x4_t(bh, sb + OFF_WH + swz(wRow, nb));
                mma16816(acc[0][bt * 2 + 0], ah0, bh[0], bh[1]);
                mma16816(acc[0][bt * 2 + 1], ah0, bh[2], bh[3]);
                mma16816(acc[1][bt * 2 + 0], ah1, bh[0], bh[1]);
                mma16816(acc[1][bt * 2 + 1], ah1, bh[2], bh[3]);
                mma16816(acc[0][bt * 2 + 0], al0, bh[0], bh[1]);
                mma16816(acc[0][bt * 2 + 1], al0, bh[2], bh[3]);
                mma16816(acc[1][bt * 2 + 0], al1, bh[0], bh[1]);
                mma16816(acc[1][bt * 2 + 1], al1, bh[2], bh[3]);
            }
        }
    }
}

// stage direct plane rows into SMEM A (full K=128)
__device__ __forceinline__ void stage_direct(
    const __half* Ah, const __half* Al,
    int m0, int tid, char* smem)
{
    int r = tid >> 1, half_ = tid & 1;
    int gr = m0 + r; if (gr > NN - 1) gr = NN - 1;
    size_t gofs = (size_t)gr * 128 + half_ * 64;
    const uint4* aph = (const uint4*)(Ah + gofs);
    const uint4* apl = (const uint4*)(Al + gofs);
    #pragma unroll
    for (int q = 0; q < 8; q++) {
        uint32_t kb = (uint32_t)(half_ * 128 + q * 16);
        uint32_t so = swz((uint32_t)r, kb);
        *(uint4*)(smem + OFF_AH + so) = aph[q];
        *(uint4*)(smem + OFF_AL + so) = apl[q];
    }
}

// epilogue: bias+relu; plane store and/or pool
__device__ __forceinline__ void epilogue(
    float acc[2][8][4], const float* sB,
    __half* outh, __half* outl,
    const int* batch, int poolOff,
    int m0, int lane, int wm, int wn)
{
    int g = lane >> 2, tg = lane & 3;
    #pragma unroll
    for (int mt = 0; mt < 2; mt++) {
        #pragma unroll
        for (int half_ = 0; half_ < 2; half_++) {
            int r = m0 + wm + mt * 16 + g + half_ * 8;
            if (r >= NN) continue;
            int bi = batch ? batch[r] : 0;
            #pragma unroll
            for (int nt = 0; nt < 8; nt++) {
                int col = wn + nt * 8 + tg * 2;
                float vx = fmaxf(acc[mt][nt][half_ * 2 + 0] + sB[col], 0.f);
                float vy = fmaxf(acc[mt][nt][half_ * 2 + 1] + sB[col + 1], 0.f);
                if (outh) {
                    __half2 hp = __floats2half2_rn(vx, vy);
                    *(uint32_t*)(outh + (size_t)r * 128 + col) = h2_bits(hp);
                    float2 hr = __half22float2(hp);
                    __half2 lp = __floats2half2_rn(vx - hr.x, vy - hr.y);
                    *(uint32_t*)(outl + (size_t)r * 128 + col) = h2_bits(lp);
                }
                if (batch) {
                    float* pp = g_pool + (size_t)bi * 256 + poolOff + col;
                    atomicAdd(pp + 0, vx);
                    atomicAdd(pp + 1, vy);
                }
            }
        }
    }
}

// ---------------- conv GEMM: relu(mean@slotL + in@slotR + bias) -> planes ----------------
__global__ __launch_bounds__(256, 2) void k_conv(
    const __half* __restrict__ inh, const __half* __restrict__ inl,
    int slotL, int slotR, const float* __restrict__ bias,
    __half* __restrict__ outh, __half* __restrict__ outl)
{
    extern __shared__ char smem[];
    uint32_t sb = smem_u32(smem);
    int tid = threadIdx.x, lane = tid & 31, wid = tid >> 5;
    int wm = (wid & 3) * 32, wn = (wid >> 2) * 64;
    int m0 = blockIdx.x * 128;
    float* sB = (float*)(smem + OFF_BI);
    if (tid < 128) sB[tid] = bias[tid];

    float acc[2][8][4];
    #pragma unroll
    for (int a = 0; a < 2; a++)
        #pragma unroll
        for (int b = 0; b < 8; b++)
            #pragma unroll
            for (int c = 0; c < 4; c++) acc[a][b][c] = 0.f;

    stage_direct(g_mh, g_ml, m0, tid, smem);
    panel_mma(acc, slotL, smem, sb, tid, lane, wm, wn);
    __syncthreads();
    stage_direct(inh, inl, m0, tid, smem);
    panel_mma(acc, slotR, smem, sb, tid, lane, wm, wn);

    epilogue(acc, sB, outh, outl, nullptr, 0, m0, lane, wm, wn);
}

// JK: relu(A1@s1 + A2@s2 + bias), plane store + pool
__global__ __launch_bounds__(256, 2) void k_gemmJK(
    const __half* __restrict__ A1h, const __half* __restrict__ A1l, int s1,
    const __half* __restrict__ A2h, const __half* __restrict__ A2l, int s2,
    const float* __restrict__ bias,
    __half* __restrict__ outh, __half* __restrict__ outl,
    const int* __restrict__ batch, int poolOff)
{
    extern __shared__ char smem[];
    uint32_t sb = smem_u32(smem);
    int tid = threadIdx.x, lane = tid & 31, wid = tid >> 5;
    int wm = (wid & 3) * 32, wn = (wid >> 2) * 64;
    int m0 = blockIdx.x * 128;
    float* sB = (float*)(smem + OFF_BI);
    if (tid < 128) sB[tid] = bias[tid];

    float acc[2][8][4];
    #pragma unroll
    for (int a = 0; a < 2; a++)
        #pragma unroll
        for (int b = 0; b < 8; b++)
            #pragma unroll
            for (int c = 0; c < 4; c++) acc[a][b][c] = 0.f;

    stage_direct(A1h, A1l, m0, tid, smem);
    panel_mma(acc, s1, smem, sb, tid, lane, wm, wn);
    __syncthreads();
    stage_direct(A2h, A2l, m0, tid, smem);
    panel_mma(acc, s2, smem, sb, tid, lane, wm, wn);

    epilogue(acc, sB, outh, outl, batch, poolOff, m0, lane, wm, wn);
}

// ---------------- head ----------------
__global__ void k_head(const float* __restrict__ gamma, const float* __restrict__ beta,
                       const float* __restrict__ rm, const float* __restrict__ rv,
                       const float* __restrict__ W1, const float* __restrict__ b1,
                       const float* __restrict__ W2, const float* __restrict__ b2,
                       float* __restrict__ out)
{
    __shared__ float sg[256];
    __shared__ float s1[128];
    __shared__ float s2[10];
    int gb = blockIdx.x, t = threadIdx.x;
    for (int i = t; i < 256; i += 128) {
        float v = g_pool[gb * 256 + i];
        v = (v - rm[i]) * rsqrtf(rv[i] + 1e-5f) * gamma[i] + beta[i];
        sg[i] = v;
    }
    __syncthreads();
    float acc = b1[t];
    #pragma unroll 8
    for (int k = 0; k < 256; k++) acc += sg[k] * W1[k * 128 + t];
    s1[t] = fmaxf(acc, 0.f);
    __syncthreads();
    if (t < 10) {
        float a = b2[t];
        #pragma unroll 8
        for (int k = 0; k < 128; k++) a += s1[k] * W2[k * 10 + t];
        s2[t] = a;
    }
    __syncthreads();
    if (t == 0) {
        float m = s2[0];
        for (int j = 1; j < 10; j++) m = fmaxf(m, s2[j]);
        float ex[10]; float sum = 0.f;
        for (int j = 0; j < 10; j++) { ex[j] = expf(s2[j] - m); sum += ex[j]; }
        float inv = 1.0f / sum;
        for (int j = 0; j < 10; j++) out[gb * 10 + j] = ex[j] * inv;
    }
}

// ---------------- host launch ----------------
extern "C" void kernel_launch(void* const* d_in, const int* in_sizes, int n_in,
                              void* d_out, int out_size)
{
    const float* x     = (const float*)d_in[0];
    const int*   ei    = (const int*)d_in[1];
    const int*   batch = (const int*)d_in[2];
    int base = (n_in > 3 && in_sizes[3] == 1) ? 4 : 3;

    const float* p[24];
    for (int i = 0; i < 24; i++) p[i] = (const float*)d_in[base + i];
    // b0: 0..7 (Wl1,Wr1,b1,Wl2,Wr2,b2,Wlin,blin); b1: 8..15; bn 16..19; lin1 20,21; lin2 22,23

    const int* src = ei;
    const int* dst = ei + EE;

    void *pxh, *pxl, *ph1h, *ph1l, *ph2h, *ph2l;
    cudaGetSymbolAddress(&pxh,  g_xh);
    cudaGetSymbolAddress(&pxl,  g_xl);
    cudaGetSymbolAddress(&ph1h, g_h1h);
    cudaGetSymbolAddress(&ph1l, g_h1l);
    cudaGetSymbolAddress(&ph2h, g_h2h);
    cudaGetSymbolAddress(&ph2l, g_h2l);

    __half* xh  = (__half*)pxh;
    __half* xl  = (__half*)pxl;
    __half* h1h = (__half*)ph1h;
    __half* h1l = (__half*)ph1l;
    __half* h2h = (__half*)ph2h;
    __half* h2l = (__half*)ph2l;

    // x planes freed after block-0 conv1 -> reuse as block-0 output (hb)
    __half* hbh = xh;
    __half* hbl = xl;

    cudaFuncSetAttribute(k_conv,   cudaFuncAttributeMaxDynamicSharedMemorySize, GEMM_SMEM);
    cudaFuncSetAttribute(k_gemmJK, cudaFuncAttributeMaxDynamicSharedMemorySize, GEMM_SMEM);

    // ---- prep (g_fill/g_pool zeroed by previous call's tail; zero-init at load) ----
    k_prep<<<13268, 256>>>(dst, x,
        p[0], p[1], p[3], p[4], p[6], p[6] + 16384,
        p[8], p[9], p[11], p[12], p[14], p[14] + 16384);
    k_scan<<<1, 1024>>>();
    k_fillcsr<<<(EE + 255) / 256, 256>>>(src, dst);

    const int AGG_BLOCKS = (NN + 7) / 8;   // 6250

    // ---- block 0, conv1 ----
    k_agg<<<AGG_BLOCKS, 256>>>(xh);
    k_conv<<<NGB, 256, GEMM_SMEM>>>(xh, xl, 0, 1, p[2], h1h, h1l);
    // ---- block 0, conv2 ----
    k_agg<<<AGG_BLOCKS, 256>>>(h1h);
    k_conv<<<NGB, 256, GEMM_SMEM>>>(h1h, h1l, 2, 3, p[5], h2h, h2l);
    // ---- block 0 JK + pool 0 (output into freed x planes) ----
    k_gemmJK<<<NGB, 256, GEMM_SMEM>>>(h1h, h1l, 4, h2h, h2l, 5, p[7], hbh, hbl, batch, 0);

    // ---- block 1, conv1 ----
    k_agg<<<AGG_BLOCKS, 256>>>(hbh);
    k_conv<<<NGB, 256, GEMM_SMEM>>>(hbh, hbl, 6, 7, p[10], h1h, h1l);
    // ---- block 1, conv2 ----
    k_agg<<<AGG_BLOCKS, 256>>>(h1h);
    k_conv<<<NGB, 256, GEMM_SMEM>>>(h1h, h1l, 8, 9, p[13], h2h, h2l);
    // ---- block 1 JK + pool 1 (pool only) ----
    k_gemmJK<<<NGB, 256, GEMM_SMEM>>>(h1h, h1l, 10, h2h, h2l, 11, p[15],
                                      nullptr, nullptr, batch, 128);

    // ---- head ----
    k_head<<<GG, 128>>>(p[16], p[17], p[18], p[19], p[20], p[21], p[22], p[23],
                        (float*)d_out);

    // ---- tail: restore zeroed state for the next call ----
    k_zero2<<<452, 256>>>();
}